// round 5
// baseline (speedup 1.0000x reference)
#include <cuda_runtime.h>
#include <math.h>

#define D 128
#define NQ 7
#define NPAIR 21

// ---------------- device-side scratch (no runtime allocation) ----------------
__device__ float  g_Hs1[NQ][4];      // single-site Hamiltonian terms (2x2)
__device__ float  g_Cs1[NQ][4];      // single-site B^T B (2x2)
__device__ float  g_Ss1[NQ][16];     // single-site superop (2^4)
__device__ float  g_Hp[NPAIR][16];   // pair Hamiltonian terms (4x4)
__device__ float  g_Cp[NPAIR][16];   // pair sum of B^T B (4x4)
__device__ float  g_Sp[NPAIR][256];  // pair superop (4^4)
__device__ float2 g_A [D*D];         // A = -iH - 0.5 M
__device__ float2 g_Ah[D*D];         // A^dagger
__device__ float2 g_rho[D*D];        // current complex state
__device__ float2 g_st0[D*D];
__device__ float2 g_st1[D*D];
__device__ float2 g_acc[D*D];

// pair tables (i<j), masks = 1<<(6-q)
__constant__ int c_pi[NPAIR] = {0,0,0,0,0,0, 1,1,1,1,1, 2,2,2,2, 3,3,3, 4,4, 5};
__constant__ int c_pj[NPAIR] = {1,2,3,4,5,6, 2,3,4,5,6, 3,4,5,6, 4,5,6, 5,6, 6};
__constant__ int c_mi[NPAIR] = {64,64,64,64,64,64, 32,32,32,32,32, 16,16,16,16, 8,8,8, 4,4, 2};
__constant__ int c_mj[NPAIR] = {32,16, 8, 4, 2, 1, 16, 8, 4, 2, 1,  8, 4, 2, 1, 4,2,1, 2,1, 1};

// ---------------- setup: MLP + small operator algebra ----------------
__global__ void prep_kernel(const float* __restrict__ features,
                            const float* __restrict__ W1, const float* __restrict__ b1,
                            const float* __restrict__ W2, const float* __restrict__ b2,
                            const float* __restrict__ Hself, const float* __restrict__ Hcoup,
                            const float* __restrict__ rates)
{
    __shared__ float s_ops[NQ][4];
    int tid = threadIdx.x;

    if (tid < NQ) {
        float f0 = features[tid*2+0], f1 = features[tid*2+1];
        float op0 = b2[0], op1 = b2[1], op2 = b2[2], op3 = b2[3];
        for (int h = 0; h < 64; h++) {
            float t = f0*W1[h] + f1*W1[64+h] + b1[h];
            t = fmaxf(t, 0.f);
            op0 += t*W2[h*4+0]; op1 += t*W2[h*4+1];
            op2 += t*W2[h*4+2]; op3 += t*W2[h*4+3];
        }
        s_ops[tid][0]=op0; s_ops[tid][1]=op1; s_ops[tid][2]=op2; s_ops[tid][3]=op3;
    }
    __syncthreads();

    if (tid < NQ) {
        int i = tid;
        const float* Hs = Hself + i*4;
        float o0=s_ops[i][0], o1=s_ops[i][1], o2=s_ops[i][2], o3=s_ops[i][3];
        float G0 = o0*Hs[0] + o1*Hs[2];
        float G1 = o0*Hs[1] + o1*Hs[3];
        float G2 = o2*Hs[0] + o3*Hs[2];
        float G3 = o2*Hs[1] + o3*Hs[3];
        g_Hs1[i][0] = 2.f*G0; g_Hs1[i][1] = G1+G2; g_Hs1[i][2] = G2+G1; g_Hs1[i][3] = 2.f*G3;
        const float* rr = rates + (i*NQ+i)*16;
        float B[4];
        B[0] = sqrtf(fabsf(rr[0]))*o0;
        B[1] = sqrtf(fabsf(rr[1]))*o1;
        B[2] = sqrtf(fabsf(rr[4]))*o2;
        B[3] = sqrtf(fabsf(rr[5]))*o3;
        g_Cs1[i][0] = B[0]*B[0]+B[2]*B[2];
        g_Cs1[i][1] = B[0]*B[1]+B[2]*B[3];
        g_Cs1[i][2] = B[1]*B[0]+B[3]*B[2];
        g_Cs1[i][3] = B[1]*B[1]+B[3]*B[3];
        for (int a=0;a<2;a++) for (int b=0;b<2;b++)
          for (int ap=0;ap<2;ap++) for (int bp=0;bp<2;bp++)
            g_Ss1[i][((a*2+b)*2+ap)*2+bp] = B[a*2+ap]*B[b*2+bp];
    }

    if (tid < NPAIR) {
        int p = tid, i = c_pi[p], j = c_pj[p];
        float K[16], B1[16], B2[16];
        for (int u=0;u<4;u++) for (int v=0;v<4;v++) {
            float kv = s_ops[i][(u>>1)*2+(v>>1)] * s_ops[j][(u&1)*2+(v&1)];
            K[u*4+v] = kv;
            B1[u*4+v] = sqrtf(fabsf(rates[(i*NQ+j)*16 + u*4+v])) * kv;
        }
        for (int u=0;u<4;u++) for (int v=0;v<4;v++) {
            int us = ((u&1)<<1)|(u>>1), vs = ((v&1)<<1)|(v>>1);
            float kv = s_ops[j][(us>>1)*2+(vs>>1)] * s_ops[i][(us&1)*2+(vs&1)];
            B2[u*4+v] = sqrtf(fabsf(rates[(j*NQ+i)*16 + us*4+vs])) * kv;
        }
        const float* Hc = Hcoup + (i*NQ+j)*16;
        float G4[16];
        for (int u=0;u<4;u++) for (int v=0;v<4;v++) {
            float s = 0.f;
            for (int k=0;k<4;k++) s += K[u*4+k]*Hc[k*4+v];
            G4[u*4+v] = s;
        }
        for (int u=0;u<4;u++) for (int v=0;v<4;v++)
            g_Hp[p][u*4+v] = G4[u*4+v] + G4[v*4+u];
        for (int u=0;u<4;u++) for (int v=0;v<4;v++) {
            float c = 0.f;
            for (int k=0;k<4;k++) c += B1[k*4+u]*B1[k*4+v] + B2[k*4+u]*B2[k*4+v];
            g_Cp[p][u*4+v] = c;
        }
        for (int u=0;u<4;u++) for (int v=0;v<4;v++)
          for (int ap=0;ap<4;ap++) for (int bp=0;bp<4;bp++)
            g_Sp[p][((u*4+v)*4+ap)*4+bp] = B1[u*4+ap]*B1[v*4+bp] + B2[u*4+ap]*B2[v*4+bp];
    }
}

// ---------------- build A = -iH - 0.5M ----------------
__global__ void build_a_kernel()
{
    int idx = blockIdx.x*blockDim.x + threadIdx.x;
    int x = idx >> 7, y = idx & 127;
    int d = x ^ y;
    float Hv = 0.f, Mv = 0.f;
    #pragma unroll
    for (int i=0;i<NQ;i++) {
        int mi = 1<<(6-i);
        if ((d & (127 ^ mi)) == 0) {
            int xl = (x>>(6-i))&1, yl = (y>>(6-i))&1;
            Hv += g_Hs1[i][xl*2+yl];
            Mv += g_Cs1[i][xl*2+yl];
        }
    }
    #pragma unroll
    for (int p=0;p<NPAIR;p++) {
        int mi = c_mi[p], mj = c_mj[p];
        if ((d & (127 ^ (mi|mj))) == 0) {
            int xl = (((x&mi)!=0)<<1)|((x&mj)!=0);
            int yl = (((y&mi)!=0)<<1)|((y&mj)!=0);
            Hv += g_Hp[p][xl*4+yl];
            Mv += g_Cp[p][xl*4+yl];
        }
    }
    g_A[idx]       = make_float2(-0.5f*Mv, -Hv);
    g_Ah[(y<<7)+x] = make_float2(-0.5f*Mv,  Hv);
}

// ---------------- init: g_rho = complex(rho0); out slice 0 = rho0 ----------------
__global__ void init_kernel(const float* __restrict__ rho0, float* __restrict__ out0)
{
    int idx = blockIdx.x*blockDim.x + threadIdx.x;
    float v = rho0[idx];
    g_rho[idx] = make_float2(v, 0.f);
    out0[idx] = v;
}

// ---------------- buffer selection ----------------
__device__ __forceinline__ const float2* rsv(int sel) {
    if (sel == 0) return g_st0;
    if (sel == 1) return g_st1;
    if (sel == 2) return g_acc;
    return g_rho;
}
__device__ __forceinline__ float2* rsvw(int sel) {
    if (sel == 0) return g_st0;
    if (sel == 1) return g_st1;
    if (sel == 2) return g_acc;
    return g_rho;
}

// ---------------- fused RHS + RK4 stage combination ----------------
// k = rhs(in); stageOut = stageBase + fs*dt*k; if fa!=0: g_acc = accBase + fa*dt*k
// if writeReal: outReal[idx] = Re(stageOut)
__global__ void __launch_bounds__(128, 1)
rhs_kernel(float* __restrict__ outReal,
           int selIn, int selSB, int selAB, int selSO, int writeReal,
           const float* __restrict__ t_eval, int step, float fs, float fa)
{
    __shared__ __align__(16) float sS[NPAIR*256];
    __shared__ float sSs[NQ*16];
    __shared__ float2 sA[D];
    __shared__ float2 sR[D];

    const float2* in = rsv(selIn);
    int x = blockIdx.x;
    int y = threadIdx.x;

    for (int k = y; k < NPAIR*256; k += 128) sS[k] = ((const float*)g_Sp)[k];
    if (y < NQ*16) sSs[y] = ((const float*)g_Ss1)[y];
    sA[y] = g_A[(x<<7)+y];
    sR[y] = in[(x<<7)+y];
    __syncthreads();

    float re = 0.f, im = 0.f;

    // dense: A rho + rho A^dagger
    #pragma unroll 4
    for (int z = 0; z < D; z++) {
        float2 a  = sA[z];
        float2 r  = __ldg(&in[(z<<7)+y]);
        re = fmaf(a.x, r.x, re); re = fmaf(-a.y, r.y, re);
        im = fmaf(a.x, r.y, im); im = fmaf( a.y, r.x, im);
        float2 bb = __ldg(&g_Ah[(z<<7)+y]);
        float2 r2 = sR[z];
        re = fmaf(r2.x, bb.x, re); re = fmaf(-r2.y, bb.y, re);
        im = fmaf(r2.x, bb.y, im); im = fmaf( r2.y, bb.x, im);
    }

    // dissipator: pair superoperators
    for (int p = 0; p < NPAIR; p++) {
        int mi = c_mi[p], mj = c_mj[p], m = mi|mj;
        int xl = (((x&mi)!=0)<<1)|((x&mj)!=0);
        int yl = (((y&mi)!=0)<<1)|((y&mj)!=0);
        int xb = (x & ~m) << 7;
        int y0 = y & ~m;
        int xr0 = xb, xr1 = xb + (mj<<7), xr2 = xb + (mi<<7), xr3 = xb + (m<<7);
        int yc0 = y0, yc1 = y0 + mj, yc2 = y0 + mi, yc3 = y0 + m;
        const float4* Sp = reinterpret_cast<const float4*>(sS + ((p*4+xl)*4+yl)*16);
        float4 s0 = Sp[0], s1 = Sp[1], s2 = Sp[2], s3 = Sp[3];
        float2 r;
        r = __ldg(&in[xr0+yc0]); re = fmaf(s0.x,r.x,re); im = fmaf(s0.x,r.y,im);
        r = __ldg(&in[xr0+yc1]); re = fmaf(s0.y,r.x,re); im = fmaf(s0.y,r.y,im);
        r = __ldg(&in[xr0+yc2]); re = fmaf(s0.z,r.x,re); im = fmaf(s0.z,r.y,im);
        r = __ldg(&in[xr0+yc3]); re = fmaf(s0.w,r.x,re); im = fmaf(s0.w,r.y,im);
        r = __ldg(&in[xr1+yc0]); re = fmaf(s1.x,r.x,re); im = fmaf(s1.x,r.y,im);
        r = __ldg(&in[xr1+yc1]); re = fmaf(s1.y,r.x,re); im = fmaf(s1.y,r.y,im);
        r = __ldg(&in[xr1+yc2]); re = fmaf(s1.z,r.x,re); im = fmaf(s1.z,r.y,im);
        r = __ldg(&in[xr1+yc3]); re = fmaf(s1.w,r.x,re); im = fmaf(s1.w,r.y,im);
        r = __ldg(&in[xr2+yc0]); re = fmaf(s2.x,r.x,re); im = fmaf(s2.x,r.y,im);
        r = __ldg(&in[xr2+yc1]); re = fmaf(s2.y,r.x,re); im = fmaf(s2.y,r.y,im);
        r = __ldg(&in[xr2+yc2]); re = fmaf(s2.z,r.x,re); im = fmaf(s2.z,r.y,im);
        r = __ldg(&in[xr2+yc3]); re = fmaf(s2.w,r.x,re); im = fmaf(s2.w,r.y,im);
        r = __ldg(&in[xr3+yc0]); re = fmaf(s3.x,r.x,re); im = fmaf(s3.x,r.y,im);
        r = __ldg(&in[xr3+yc1]); re = fmaf(s3.y,r.x,re); im = fmaf(s3.y,r.y,im);
        r = __ldg(&in[xr3+yc2]); re = fmaf(s3.z,r.x,re); im = fmaf(s3.z,r.y,im);
        r = __ldg(&in[xr3+yc3]); re = fmaf(s3.w,r.x,re); im = fmaf(s3.w,r.y,im);
    }

    // dissipator: single-site superoperators
    #pragma unroll
    for (int i = 0; i < NQ; i++) {
        int mi = 1<<(6-i);
        int xl = (x&mi)!=0, yl = (y&mi)!=0;
        int xb = (x & ~mi) << 7;
        int y0 = y & ~mi;
        const float* Ss = sSs + i*16 + (xl*2+yl)*4;
        float2 r;
        r = __ldg(&in[xb + y0]);                re = fmaf(Ss[0],r.x,re); im = fmaf(Ss[0],r.y,im);
        r = __ldg(&in[xb + y0 + mi]);           re = fmaf(Ss[1],r.x,re); im = fmaf(Ss[1],r.y,im);
        r = __ldg(&in[xb + (mi<<7) + y0]);      re = fmaf(Ss[2],r.x,re); im = fmaf(Ss[2],r.y,im);
        r = __ldg(&in[xb + (mi<<7) + y0 + mi]); re = fmaf(Ss[3],r.x,re); im = fmaf(Ss[3],r.y,im);
    }

    // RK4 stage combination
    int idx = (x<<7) + y;
    float dt = __ldg(&t_eval[step+1]) - __ldg(&t_eval[step]);
    const float2* sb = rsv(selSB);
    float2* so = rsvw(selSO);
    float cs = fs*dt;
    float2 sv = sb[idx];
    float2 ov = make_float2(fmaf(cs, re, sv.x), fmaf(cs, im, sv.y));
    so[idx] = ov;
    if (writeReal) outReal[idx] = ov.x;
    if (fa != 0.f) {
        const float2* ab = rsv(selAB);
        float2 av = ab[idx];
        float ca = fa*dt;
        g_acc[idx] = make_float2(fmaf(ca, re, av.x), fmaf(ca, im, av.y));
    }
}

// ---------------- launcher ----------------
extern "C" void kernel_launch(void* const* d_in, const int* in_sizes, int n_in,
                              void* d_out, int out_size)
{
    const float *features=0, *t_eval=0, *W1=0, *b1=0, *W2=0, *b2=0;
    const float *Hself=0, *Hcoup=0, *rates=0, *rho0=0;
    int n784 = 0;
    for (int i = 0; i < n_in; i++) {
        const float* p = (const float*)d_in[i];
        switch (in_sizes[i]) {
            case 14:    features = p; break;
            case 5:     t_eval   = p; break;
            case 128:   W1       = p; break;
            case 64:    b1       = p; break;
            case 256:   W2       = p; break;
            case 4:     b2       = p; break;
            case 28:    Hself    = p; break;
            case 784:   if (n784++ == 0) Hcoup = p; else rates = p; break;
            case 16384: rho0     = p; break;
            default: break;
        }
    }
    if (!features) features = (const float*)d_in[0];
    if (!t_eval)   t_eval   = (const float*)d_in[1];
    if (!W1)       W1       = (const float*)d_in[2];
    if (!b1)       b1       = (const float*)d_in[3];
    if (!W2)       W2       = (const float*)d_in[4];
    if (!b2)       b2       = (const float*)d_in[5];
    if (!Hself)    Hself    = (const float*)d_in[6];
    if (!Hcoup)    Hcoup    = (const float*)d_in[7];
    if (!rates)    rates    = (const float*)d_in[8];
    if (!rho0)     rho0     = (const float*)d_in[9];

    float* out = (float*)d_out;   // float32 real output, (5,128,128)

    prep_kernel<<<1, 32>>>(features, W1, b1, W2, b2, Hself, Hcoup, rates);
    build_a_kernel<<<64, 256>>>();
    init_kernel<<<64, 256>>>(rho0, out);

    // sel codes: 0 = g_st0, 1 = g_st1, 2 = g_acc, 3 = g_rho
    for (int t = 0; t < 4; t++) {
        float* outSlice = out + (t+1)*D*D;
        // k1: in=rho, st0 = rho+0.5dt k1, acc = rho + dt/6 k1
        rhs_kernel<<<D, D>>>(outSlice, 3, 3, 3, 0, 0, t_eval, t, 0.5f, 1.f/6.f);
        // k2: in=st0, st1 = rho+0.5dt k2, acc += dt/3 k2
        rhs_kernel<<<D, D>>>(outSlice, 0, 3, 2, 1, 0, t_eval, t, 0.5f, 1.f/3.f);
        // k3: in=st1, st0 = rho+dt k3, acc += dt/3 k3
        rhs_kernel<<<D, D>>>(outSlice, 1, 3, 2, 0, 0, t_eval, t, 1.0f, 1.f/3.f);
        // k4: in=st0, rho = acc + dt/6 k4; write Re(rho) to out slice t+1
        rhs_kernel<<<D, D>>>(outSlice, 0, 2, 2, 3, 1, t_eval, t, 1.f/6.f, 0.f);
    }
    (void)out_size;
}

// round 6
// speedup vs baseline: 1.7397x; 1.7397x over previous
#include <cuda_runtime.h>
#include <math.h>

#define D 128
#define NQ 7
#define NPAIR 21

// ---------------- device-side scratch (no runtime allocation) ----------------
__device__ float  g_Hs1[NQ][4];
__device__ float  g_Cs1[NQ][4];
__device__ float  g_Ss1[NQ][16];
__device__ float  g_Hp[NPAIR][16];
__device__ float  g_Cp[NPAIR][16];
__device__ float  g_Sp[NPAIR][256];
__device__ __align__(16) float2 g_A [D*D];
__device__ __align__(16) float2 g_Ah[D*D];
__device__ __align__(16) float2 g_rho[D*D];
__device__ __align__(16) float2 g_st0[D*D];
__device__ __align__(16) float2 g_st1[D*D];
__device__ __align__(16) float2 g_acc[D*D];

__constant__ int c_pi[NPAIR] = {0,0,0,0,0,0, 1,1,1,1,1, 2,2,2,2, 3,3,3, 4,4, 5};
__constant__ int c_pj[NPAIR] = {1,2,3,4,5,6, 2,3,4,5,6, 3,4,5,6, 4,5,6, 5,6, 6};
__constant__ int c_mi[NPAIR] = {64,64,64,64,64,64, 32,32,32,32,32, 16,16,16,16, 8,8,8, 4,4, 2};
__constant__ int c_mj[NPAIR] = {32,16, 8, 4, 2, 1, 16, 8, 4, 2, 1,  8, 4, 2, 1, 4,2,1, 2,1, 1};

// dynamic smem layout (bytes)
#define SM_RHO   0          // float2[16384] = 131072
#define SM_A     131072     // float2[128]   = 1024
#define SM_PART  132096     // float2[128]   = 1024
#define SM_SX    133120     // float[21*64]  = 5376
#define SM_SSX   138496     // float[7*8]    = 224
#define SMEM_BYTES 138752

// ---------------- setup: MLP + small operator algebra ----------------
__global__ void prep_kernel(const float* __restrict__ features,
                            const float* __restrict__ W1, const float* __restrict__ b1,
                            const float* __restrict__ W2, const float* __restrict__ b2,
                            const float* __restrict__ Hself, const float* __restrict__ Hcoup,
                            const float* __restrict__ rates)
{
    __shared__ float s_ops[NQ][4];
    int tid = threadIdx.x;

    if (tid < NQ) {
        float f0 = features[tid*2+0], f1 = features[tid*2+1];
        float op0 = b2[0], op1 = b2[1], op2 = b2[2], op3 = b2[3];
        for (int h = 0; h < 64; h++) {
            float t = f0*W1[h] + f1*W1[64+h] + b1[h];
            t = fmaxf(t, 0.f);
            op0 += t*W2[h*4+0]; op1 += t*W2[h*4+1];
            op2 += t*W2[h*4+2]; op3 += t*W2[h*4+3];
        }
        s_ops[tid][0]=op0; s_ops[tid][1]=op1; s_ops[tid][2]=op2; s_ops[tid][3]=op3;
    }
    __syncthreads();

    if (tid < NQ) {
        int i = tid;
        const float* Hs = Hself + i*4;
        float o0=s_ops[i][0], o1=s_ops[i][1], o2=s_ops[i][2], o3=s_ops[i][3];
        float G0 = o0*Hs[0] + o1*Hs[2];
        float G1 = o0*Hs[1] + o1*Hs[3];
        float G2 = o2*Hs[0] + o3*Hs[2];
        float G3 = o2*Hs[1] + o3*Hs[3];
        g_Hs1[i][0] = 2.f*G0; g_Hs1[i][1] = G1+G2; g_Hs1[i][2] = G2+G1; g_Hs1[i][3] = 2.f*G3;
        const float* rr = rates + (i*NQ+i)*16;
        float B[4];
        B[0] = sqrtf(fabsf(rr[0]))*o0;
        B[1] = sqrtf(fabsf(rr[1]))*o1;
        B[2] = sqrtf(fabsf(rr[4]))*o2;
        B[3] = sqrtf(fabsf(rr[5]))*o3;
        g_Cs1[i][0] = B[0]*B[0]+B[2]*B[2];
        g_Cs1[i][1] = B[0]*B[1]+B[2]*B[3];
        g_Cs1[i][2] = B[1]*B[0]+B[3]*B[2];
        g_Cs1[i][3] = B[1]*B[1]+B[3]*B[3];
        for (int a=0;a<2;a++) for (int b=0;b<2;b++)
          for (int ap=0;ap<2;ap++) for (int bp=0;bp<2;bp++)
            g_Ss1[i][((a*2+b)*2+ap)*2+bp] = B[a*2+ap]*B[b*2+bp];
    }

    if (tid < NPAIR) {
        int p = tid, i = c_pi[p], j = c_pj[p];
        float K[16], B1[16], B2[16];
        for (int u=0;u<4;u++) for (int v=0;v<4;v++) {
            float kv = s_ops[i][(u>>1)*2+(v>>1)] * s_ops[j][(u&1)*2+(v&1)];
            K[u*4+v] = kv;
            B1[u*4+v] = sqrtf(fabsf(rates[(i*NQ+j)*16 + u*4+v])) * kv;
        }
        for (int u=0;u<4;u++) for (int v=0;v<4;v++) {
            int us = ((u&1)<<1)|(u>>1), vs = ((v&1)<<1)|(v>>1);
            float kv = s_ops[j][(us>>1)*2+(vs>>1)] * s_ops[i][(us&1)*2+(vs&1)];
            B2[u*4+v] = sqrtf(fabsf(rates[(j*NQ+i)*16 + us*4+vs])) * kv;
        }
        const float* Hc = Hcoup + (i*NQ+j)*16;
        float G4[16];
        for (int u=0;u<4;u++) for (int v=0;v<4;v++) {
            float s = 0.f;
            for (int k=0;k<4;k++) s += K[u*4+k]*Hc[k*4+v];
            G4[u*4+v] = s;
        }
        for (int u=0;u<4;u++) for (int v=0;v<4;v++)
            g_Hp[p][u*4+v] = G4[u*4+v] + G4[v*4+u];
        for (int u=0;u<4;u++) for (int v=0;v<4;v++) {
            float c = 0.f;
            for (int k=0;k<4;k++) c += B1[k*4+u]*B1[k*4+v] + B2[k*4+u]*B2[k*4+v];
            g_Cp[p][u*4+v] = c;
        }
        for (int u=0;u<4;u++) for (int v=0;v<4;v++)
          for (int ap=0;ap<4;ap++) for (int bp=0;bp<4;bp++)
            g_Sp[p][((u*4+v)*4+ap)*4+bp] = B1[u*4+ap]*B1[v*4+bp] + B2[u*4+ap]*B2[v*4+bp];
    }
}

// ---------------- build A = -iH - 0.5M ----------------
__global__ void build_a_kernel()
{
    int idx = blockIdx.x*blockDim.x + threadIdx.x;
    int x = idx >> 7, y = idx & 127;
    int d = x ^ y;
    float Hv = 0.f, Mv = 0.f;
    #pragma unroll
    for (int i=0;i<NQ;i++) {
        int mi = 1<<(6-i);
        if ((d & (127 ^ mi)) == 0) {
            int xl = (x>>(6-i))&1, yl = (y>>(6-i))&1;
            Hv += g_Hs1[i][xl*2+yl];
            Mv += g_Cs1[i][xl*2+yl];
        }
    }
    #pragma unroll
    for (int p=0;p<NPAIR;p++) {
        int mi = c_mi[p], mj = c_mj[p];
        if ((d & (127 ^ (mi|mj))) == 0) {
            int xl = (((x&mi)!=0)<<1)|((x&mj)!=0);
            int yl = (((y&mi)!=0)<<1)|((y&mj)!=0);
            Hv += g_Hp[p][xl*4+yl];
            Mv += g_Cp[p][xl*4+yl];
        }
    }
    g_A[idx]       = make_float2(-0.5f*Mv, -Hv);
    g_Ah[(y<<7)+x] = make_float2(-0.5f*Mv,  Hv);
}

// ---------------- init: g_rho = complex(rho0); out slice 0 = rho0 ----------------
__global__ void init_kernel(const float* __restrict__ rho0, float* __restrict__ out0)
{
    int idx = blockIdx.x*blockDim.x + threadIdx.x;
    float v = rho0[idx];
    g_rho[idx] = make_float2(v, 0.f);
    out0[idx] = v;
}

// ---------------- buffer selection ----------------
__device__ __forceinline__ const float2* rsv(int sel) {
    if (sel == 0) return g_st0;
    if (sel == 1) return g_st1;
    if (sel == 2) return g_acc;
    return g_rho;
}
__device__ __forceinline__ float2* rsvw(int sel) {
    if (sel == 0) return g_st0;
    if (sel == 1) return g_st1;
    if (sel == 2) return g_acc;
    return g_rho;
}

// ---------------- fused RHS + RK4 stage combination ----------------
// Thread (y, h): h=0/1 split the dense z-range and dissipator terms; smem reduce.
// k = rhs(in); stageOut = stageBase + fs*dt*k; if fa!=0: g_acc = accBase + fa*dt*k
__global__ void __launch_bounds__(256, 1)
rhs_kernel(float* __restrict__ outReal,
           int selIn, int selSB, int selAB, int selSO, int writeReal,
           const float* __restrict__ t_eval, int step, float fs, float fa)
{
    extern __shared__ __align__(16) char smem[];
    float2* sRho  = (float2*)(smem + SM_RHO);
    float2* sA    = (float2*)(smem + SM_A);
    float2* sPart = (float2*)(smem + SM_PART);
    float*  sSx   = (float*)(smem + SM_SX);
    float*  sSsx  = (float*)(smem + SM_SSX);

    const float2* in = rsv(selIn);
    int x   = blockIdx.x;
    int tid = threadIdx.x;
    int y   = tid & 127;
    int h   = tid >> 7;

    // stage full rho into smem (float4 vectorized: 8192 float4 / 256 threads)
    {
        const float4* inv = (const float4*)in;
        float4* srv = (float4*)sRho;
        #pragma unroll
        for (int k = 0; k < 32; k++) srv[tid + (k<<8)] = __ldg(&inv[tid + (k<<8)]);
    }
    if (h == 0) sA[y] = g_A[(x<<7)+y];
    // stage xl-slice of pair superops: sSx[p*64 + yl*16 + e]
    for (int k = tid; k < NPAIR*64; k += 256) {
        int p = k >> 6;
        int mi = c_mi[p], mj = c_mj[p];
        int xl = (((x&mi)!=0)<<1)|((x&mj)!=0);
        sSx[k] = g_Sp[p][xl*64 + (k & 63)];
    }
    // stage xl-slice of single-site superops: sSsx[i*8 + yl*4 + e]
    if (tid < NQ*8) {
        int i = tid >> 3;
        int mi = 1<<(6-i);
        int xl = (x & mi) != 0;
        sSsx[tid] = g_Ss1[i][xl*8 + (tid & 7)];
    }
    __syncthreads();

    float re = 0.f, im = 0.f;

    // dense: A rho + rho A^dagger, z split by h
    {
        int zbase = h << 6;
        #pragma unroll 4
        for (int zz = 0; zz < 64; zz++) {
            int z = zbase + zz;
            float2 a  = sA[z];
            float2 r  = sRho[(z<<7)+y];
            re = fmaf(a.x, r.x, re); re = fmaf(-a.y, r.y, re);
            im = fmaf(a.x, r.y, im); im = fmaf( a.y, r.x, im);
            float2 bb = __ldg(&g_Ah[(z<<7)+y]);
            float2 r2 = sRho[(x<<7)+z];
            re = fmaf(r2.x, bb.x, re); re = fmaf(-r2.y, bb.y, re);
            im = fmaf(r2.x, bb.y, im); im = fmaf( r2.y, bb.x, im);
        }
    }

    // dissipator: pair superoperators, split 11/10 by h
    {
        int p0 = h ? 11 : 0, p1 = h ? NPAIR : 11;
        for (int p = p0; p < p1; p++) {
            int mi = c_mi[p], mj = c_mj[p], m = mi|mj;
            int yl = (((y&mi)!=0)<<1)|((y&mj)!=0);
            int xb = (x & ~m) << 7;
            int y0 = y & ~m;
            int xr0 = xb, xr1 = xb + (mj<<7), xr2 = xb + (mi<<7), xr3 = xb + (m<<7);
            int yc0 = y0, yc1 = y0 + mj, yc2 = y0 + mi, yc3 = y0 + m;
            const float4* Sp = reinterpret_cast<const float4*>(sSx + p*64 + yl*16);
            float4 s0 = Sp[0], s1 = Sp[1], s2 = Sp[2], s3 = Sp[3];
            float2 r;
            r = sRho[xr0+yc0]; re = fmaf(s0.x,r.x,re); im = fmaf(s0.x,r.y,im);
            r = sRho[xr0+yc1]; re = fmaf(s0.y,r.x,re); im = fmaf(s0.y,r.y,im);
            r = sRho[xr0+yc2]; re = fmaf(s0.z,r.x,re); im = fmaf(s0.z,r.y,im);
            r = sRho[xr0+yc3]; re = fmaf(s0.w,r.x,re); im = fmaf(s0.w,r.y,im);
            r = sRho[xr1+yc0]; re = fmaf(s1.x,r.x,re); im = fmaf(s1.x,r.y,im);
            r = sRho[xr1+yc1]; re = fmaf(s1.y,r.x,re); im = fmaf(s1.y,r.y,im);
            r = sRho[xr1+yc2]; re = fmaf(s1.z,r.x,re); im = fmaf(s1.z,r.y,im);
            r = sRho[xr1+yc3]; re = fmaf(s1.w,r.x,re); im = fmaf(s1.w,r.y,im);
            r = sRho[xr2+yc0]; re = fmaf(s2.x,r.x,re); im = fmaf(s2.x,r.y,im);
            r = sRho[xr2+yc1]; re = fmaf(s2.y,r.x,re); im = fmaf(s2.y,r.y,im);
            r = sRho[xr2+yc2]; re = fmaf(s2.z,r.x,re); im = fmaf(s2.z,r.y,im);
            r = sRho[xr2+yc3]; re = fmaf(s2.w,r.x,re); im = fmaf(s2.w,r.y,im);
            r = sRho[xr3+yc0]; re = fmaf(s3.x,r.x,re); im = fmaf(s3.x,r.y,im);
            r = sRho[xr3+yc1]; re = fmaf(s3.y,r.x,re); im = fmaf(s3.y,r.y,im);
            r = sRho[xr3+yc2]; re = fmaf(s3.z,r.x,re); im = fmaf(s3.z,r.y,im);
            r = sRho[xr3+yc3]; re = fmaf(s3.w,r.x,re); im = fmaf(s3.w,r.y,im);
        }
    }

    // dissipator: single-site superoperators, split 4/3 by h
    {
        int i0 = h ? 4 : 0, i1 = h ? NQ : 4;
        for (int i = i0; i < i1; i++) {
            int mi = 1<<(6-i);
            int yl = (y&mi)!=0;
            int xb = (x & ~mi) << 7;
            int y0 = y & ~mi;
            const float* Ss = sSsx + i*8 + yl*4;
            float s0 = Ss[0], s1 = Ss[1], s2 = Ss[2], s3 = Ss[3];
            float2 r;
            r = sRho[xb + y0];                re = fmaf(s0,r.x,re); im = fmaf(s0,r.y,im);
            r = sRho[xb + y0 + mi];           re = fmaf(s1,r.x,re); im = fmaf(s1,r.y,im);
            r = sRho[xb + (mi<<7) + y0];      re = fmaf(s2,r.x,re); im = fmaf(s2,r.y,im);
            r = sRho[xb + (mi<<7) + y0 + mi]; re = fmaf(s3,r.x,re); im = fmaf(s3,r.y,im);
        }
    }

    // reduce the two halves, then RK4 stage combination (h == 0 threads)
    if (h == 1) sPart[y] = make_float2(re, im);
    __syncthreads();
    if (h == 0) {
        float2 pp = sPart[y];
        re += pp.x; im += pp.y;
        int idx = (x<<7) + y;
        float dt = __ldg(&t_eval[step+1]) - __ldg(&t_eval[step]);
        const float2* sb = rsv(selSB);
        float2* so = rsvw(selSO);
        float cs = fs*dt;
        float2 sv = __ldg(&sb[idx]);
        float2 ov = make_float2(fmaf(cs, re, sv.x), fmaf(cs, im, sv.y));
        so[idx] = ov;
        if (writeReal) outReal[idx] = ov.x;
        if (fa != 0.f) {
            const float2* ab = rsv(selAB);
            float2 av = __ldg(&ab[idx]);
            float ca = fa*dt;
            g_acc[idx] = make_float2(fmaf(ca, re, av.x), fmaf(ca, im, av.y));
        }
    }
}

// ---------------- launcher ----------------
extern "C" void kernel_launch(void* const* d_in, const int* in_sizes, int n_in,
                              void* d_out, int out_size)
{
    const float *features=0, *t_eval=0, *W1=0, *b1=0, *W2=0, *b2=0;
    const float *Hself=0, *Hcoup=0, *rates=0, *rho0=0;
    int n784 = 0;
    for (int i = 0; i < n_in; i++) {
        const float* p = (const float*)d_in[i];
        switch (in_sizes[i]) {
            case 14:    features = p; break;
            case 5:     t_eval   = p; break;
            case 128:   W1       = p; break;
            case 64:    b1       = p; break;
            case 256:   W2       = p; break;
            case 4:     b2       = p; break;
            case 28:    Hself    = p; break;
            case 784:   if (n784++ == 0) Hcoup = p; else rates = p; break;
            case 16384: rho0     = p; break;
            default: break;
        }
    }
    if (!features) features = (const float*)d_in[0];
    if (!t_eval)   t_eval   = (const float*)d_in[1];
    if (!W1)       W1       = (const float*)d_in[2];
    if (!b1)       b1       = (const float*)d_in[3];
    if (!W2)       W2       = (const float*)d_in[4];
    if (!b2)       b2       = (const float*)d_in[5];
    if (!Hself)    Hself    = (const float*)d_in[6];
    if (!Hcoup)    Hcoup    = (const float*)d_in[7];
    if (!rates)    rates    = (const float*)d_in[8];
    if (!rho0)     rho0     = (const float*)d_in[9];

    float* out = (float*)d_out;   // float32 real output, (5,128,128)

    static int attrDone = 0;
    if (!attrDone) {
        cudaFuncSetAttribute(rhs_kernel, cudaFuncAttributeMaxDynamicSharedMemorySize, SMEM_BYTES);
        attrDone = 1;
    }

    prep_kernel<<<1, 32>>>(features, W1, b1, W2, b2, Hself, Hcoup, rates);
    build_a_kernel<<<64, 256>>>();
    init_kernel<<<64, 256>>>(rho0, out);

    // sel codes: 0 = g_st0, 1 = g_st1, 2 = g_acc, 3 = g_rho
    for (int t = 0; t < 4; t++) {
        float* outSlice = out + (t+1)*D*D;
        // k1: in=rho, st0 = rho+0.5dt k1, acc = rho + dt/6 k1
        rhs_kernel<<<D, 256, SMEM_BYTES>>>(outSlice, 3, 3, 3, 0, 0, t_eval, t, 0.5f, 1.f/6.f);
        // k2: in=st0, st1 = rho+0.5dt k2, acc += dt/3 k2
        rhs_kernel<<<D, 256, SMEM_BYTES>>>(outSlice, 0, 3, 2, 1, 0, t_eval, t, 0.5f, 1.f/3.f);
        // k3: in=st1, st0 = rho+dt k3, acc += dt/3 k3
        rhs_kernel<<<D, 256, SMEM_BYTES>>>(outSlice, 1, 3, 2, 0, 0, t_eval, t, 1.0f, 1.f/3.f);
        // k4: in=st0, rho = acc + dt/6 k4; write Re(rho) to out slice t+1
        rhs_kernel<<<D, 256, SMEM_BYTES>>>(outSlice, 0, 2, 2, 3, 1, t_eval, t, 1.f/6.f, 0.f);
    }
    (void)out_size;
}

// round 7
// speedup vs baseline: 2.1090x; 1.2123x over previous
#include <cuda_runtime.h>
#include <math.h>

#define D 128
#define NQ 7
#define NPAIR 21
#define NOFF 29   // 1 + 7 + 21 sparse offsets of A

// ---------------- device-side scratch (no runtime allocation) ----------------
__device__ float  g_Hs1[NQ][4];
__device__ float  g_Cs1[NQ][4];
__device__ float  g_Ss1[NQ][16];
__device__ float  g_Hp[NPAIR][16];
__device__ float  g_Cp[NPAIR][16];
__device__ float  g_Sp[NPAIR][256];
__device__ __align__(16) float2 g_A   [D*D];       // dense A = -iH - 0.5M
__device__ __align__(16) float2 g_Arow[NOFF*D];    // Arow[k][x] = A[x][x^d_k]
__device__ __align__(16) float2 g_Acol[NOFF*D];    // Acol[k][y] = conj(A[y][y^d_k])
__device__ __align__(16) float2 g_rho[D*D];
__device__ __align__(16) float2 g_st0[D*D];
__device__ __align__(16) float2 g_st1[D*D];
__device__ __align__(16) float2 g_acc[D*D];

__constant__ int c_pi[NPAIR] = {0,0,0,0,0,0, 1,1,1,1,1, 2,2,2,2, 3,3,3, 4,4, 5};
__constant__ int c_pj[NPAIR] = {1,2,3,4,5,6, 2,3,4,5,6, 3,4,5,6, 4,5,6, 5,6, 6};
__constant__ int c_mi[NPAIR] = {64,64,64,64,64,64, 32,32,32,32,32, 16,16,16,16, 8,8,8, 4,4, 2};
__constant__ int c_mj[NPAIR] = {32,16, 8, 4, 2, 1, 16, 8, 4, 2, 1,  8, 4, 2, 1, 4,2,1, 2,1, 1};
// sparse offsets: 0, single bits, pair masks
__constant__ int c_d[NOFF] = {0, 64,32,16,8,4,2,1,
    96,80,72,68,66,65, 48,40,36,34,33, 24,20,18,17, 12,10,9, 6,5, 3};

// dynamic smem layout (bytes)
#define SM_RHO    0                         // float2[16384] = 131072
#define SM_ACOL   131072                    // float2[29*128] = 29696
#define SM_AROW   160768                    // float2[32] pad   = 256
#define SM_PART   161024                    // float2[3*128]  = 3072
#define SM_SX     164096                    // float[21*64]   = 5376
#define SM_SSX    169472                    // float[7*8]     = 224
#define SMEM_BYTES 169728

// ---------------- setup: MLP + small operator algebra ----------------
__global__ void prep_kernel(const float* __restrict__ features,
                            const float* __restrict__ W1, const float* __restrict__ b1,
                            const float* __restrict__ W2, const float* __restrict__ b2,
                            const float* __restrict__ Hself, const float* __restrict__ Hcoup,
                            const float* __restrict__ rates)
{
    __shared__ float s_ops[NQ][4];
    int tid = threadIdx.x;

    if (tid < NQ) {
        float f0 = features[tid*2+0], f1 = features[tid*2+1];
        float op0 = b2[0], op1 = b2[1], op2 = b2[2], op3 = b2[3];
        for (int h = 0; h < 64; h++) {
            float t = f0*W1[h] + f1*W1[64+h] + b1[h];
            t = fmaxf(t, 0.f);
            op0 += t*W2[h*4+0]; op1 += t*W2[h*4+1];
            op2 += t*W2[h*4+2]; op3 += t*W2[h*4+3];
        }
        s_ops[tid][0]=op0; s_ops[tid][1]=op1; s_ops[tid][2]=op2; s_ops[tid][3]=op3;
    }
    __syncthreads();

    if (tid < NQ) {
        int i = tid;
        const float* Hs = Hself + i*4;
        float o0=s_ops[i][0], o1=s_ops[i][1], o2=s_ops[i][2], o3=s_ops[i][3];
        float G0 = o0*Hs[0] + o1*Hs[2];
        float G1 = o0*Hs[1] + o1*Hs[3];
        float G2 = o2*Hs[0] + o3*Hs[2];
        float G3 = o2*Hs[1] + o3*Hs[3];
        g_Hs1[i][0] = 2.f*G0; g_Hs1[i][1] = G1+G2; g_Hs1[i][2] = G2+G1; g_Hs1[i][3] = 2.f*G3;
        const float* rr = rates + (i*NQ+i)*16;
        float B[4];
        B[0] = sqrtf(fabsf(rr[0]))*o0;
        B[1] = sqrtf(fabsf(rr[1]))*o1;
        B[2] = sqrtf(fabsf(rr[4]))*o2;
        B[3] = sqrtf(fabsf(rr[5]))*o3;
        g_Cs1[i][0] = B[0]*B[0]+B[2]*B[2];
        g_Cs1[i][1] = B[0]*B[1]+B[2]*B[3];
        g_Cs1[i][2] = B[1]*B[0]+B[3]*B[2];
        g_Cs1[i][3] = B[1]*B[1]+B[3]*B[3];
        for (int a=0;a<2;a++) for (int b=0;b<2;b++)
          for (int ap=0;ap<2;ap++) for (int bp=0;bp<2;bp++)
            g_Ss1[i][((a*2+b)*2+ap)*2+bp] = B[a*2+ap]*B[b*2+bp];
    }

    if (tid < NPAIR) {
        int p = tid, i = c_pi[p], j = c_pj[p];
        float K[16], B1[16], B2[16];
        for (int u=0;u<4;u++) for (int v=0;v<4;v++) {
            float kv = s_ops[i][(u>>1)*2+(v>>1)] * s_ops[j][(u&1)*2+(v&1)];
            K[u*4+v] = kv;
            B1[u*4+v] = sqrtf(fabsf(rates[(i*NQ+j)*16 + u*4+v])) * kv;
        }
        for (int u=0;u<4;u++) for (int v=0;v<4;v++) {
            int us = ((u&1)<<1)|(u>>1), vs = ((v&1)<<1)|(v>>1);
            float kv = s_ops[j][(us>>1)*2+(vs>>1)] * s_ops[i][(us&1)*2+(vs&1)];
            B2[u*4+v] = sqrtf(fabsf(rates[(j*NQ+i)*16 + us*4+vs])) * kv;
        }
        const float* Hc = Hcoup + (i*NQ+j)*16;
        float G4[16];
        for (int u=0;u<4;u++) for (int v=0;v<4;v++) {
            float s = 0.f;
            for (int k=0;k<4;k++) s += K[u*4+k]*Hc[k*4+v];
            G4[u*4+v] = s;
        }
        for (int u=0;u<4;u++) for (int v=0;v<4;v++)
            g_Hp[p][u*4+v] = G4[u*4+v] + G4[v*4+u];
        for (int u=0;u<4;u++) for (int v=0;v<4;v++) {
            float c = 0.f;
            for (int k=0;k<4;k++) c += B1[k*4+u]*B1[k*4+v] + B2[k*4+u]*B2[k*4+v];
            g_Cp[p][u*4+v] = c;
        }
        for (int u=0;u<4;u++) for (int v=0;v<4;v++)
          for (int ap=0;ap<4;ap++) for (int bp=0;bp<4;bp++)
            g_Sp[p][((u*4+v)*4+ap)*4+bp] = B1[u*4+ap]*B1[v*4+bp] + B2[u*4+ap]*B2[v*4+bp];
    }
}

// ---------------- build A = -iH - 0.5M (dense) ----------------
__global__ void build_a_kernel()
{
    int idx = blockIdx.x*blockDim.x + threadIdx.x;
    int x = idx >> 7, y = idx & 127;
    int d = x ^ y;
    float Hv = 0.f, Mv = 0.f;
    #pragma unroll
    for (int i=0;i<NQ;i++) {
        int mi = 1<<(6-i);
        if ((d & (127 ^ mi)) == 0) {
            int xl = (x>>(6-i))&1, yl = (y>>(6-i))&1;
            Hv += g_Hs1[i][xl*2+yl];
            Mv += g_Cs1[i][xl*2+yl];
        }
    }
    #pragma unroll
    for (int p=0;p<NPAIR;p++) {
        int mi = c_mi[p], mj = c_mj[p];
        if ((d & (127 ^ (mi|mj))) == 0) {
            int xl = (((x&mi)!=0)<<1)|((x&mj)!=0);
            int yl = (((y&mi)!=0)<<1)|((y&mj)!=0);
            Hv += g_Hp[p][xl*4+yl];
            Mv += g_Cp[p][xl*4+yl];
        }
    }
    g_A[idx] = make_float2(-0.5f*Mv, -Hv);
}

// ---------------- extract sparse rows/cols of A ----------------
__global__ void build_sparse_kernel()
{
    int idx = blockIdx.x*blockDim.x + threadIdx.x;   // NOFF*128 threads
    if (idx >= NOFF*D) return;
    int k = idx >> 7, i = idx & 127;
    int d = c_d[k];
    float2 a = g_A[(i<<7) + (i^d)];
    g_Arow[idx] = a;                          // A[i][i^d]
    g_Acol[idx] = make_float2(a.x, -a.y);     // conj(A[i][i^d])
}

// ---------------- init: g_rho = complex(rho0); out slice 0 = rho0 ----------------
__global__ void init_kernel(const float* __restrict__ rho0, float* __restrict__ out0)
{
    int idx = blockIdx.x*blockDim.x + threadIdx.x;
    float v = rho0[idx];
    g_rho[idx] = make_float2(v, 0.f);
    out0[idx] = v;
}

// ---------------- buffer selection ----------------
__device__ __forceinline__ const float2* rsv(int sel) {
    if (sel == 0) return g_st0;
    if (sel == 1) return g_st1;
    if (sel == 2) return g_acc;
    return g_rho;
}
__device__ __forceinline__ float2* rsvw(int sel) {
    if (sel == 0) return g_st0;
    if (sel == 1) return g_st1;
    if (sel == 2) return g_acc;
    return g_rho;
}

// work split tables for quarter q = tid>>7
__constant__ int c_k0[4] = {0, 8, 16, 23};
__constant__ int c_k1[4] = {8, 16, 23, 29};
__constant__ int c_p0[4] = {0, 5, 10, 15};
__constant__ int c_p1[4] = {5, 10, 15, 21};
__constant__ int c_s0[4] = {0, 2, 4, 6};
__constant__ int c_s1[4] = {2, 4, 6, 7};

// ---------------- fused RHS + RK4 stage combination ----------------
__global__ void __launch_bounds__(512, 1)
rhs_kernel(float* __restrict__ outReal,
           int selIn, int selSB, int selAB, int selSO, int writeReal,
           const float* __restrict__ t_eval, int step, float fs, float fa)
{
    extern __shared__ __align__(16) char smem[];
    float2* sRho   = (float2*)(smem + SM_RHO);
    float2* sAcol  = (float2*)(smem + SM_ACOL);
    float2* sArow  = (float2*)(smem + SM_AROW);
    float2* sPart  = (float2*)(smem + SM_PART);
    float*  sSx    = (float*)(smem + SM_SX);
    float*  sSsx   = (float*)(smem + SM_SSX);

    const float2* in = rsv(selIn);
    int x   = blockIdx.x;
    int tid = threadIdx.x;
    int y   = tid & 127;
    int q   = tid >> 7;

    // stage rho (8192 float4 / 512 threads = 16 each)
    {
        const float4* inv = (const float4*)in;
        float4* srv = (float4*)sRho;
        #pragma unroll
        for (int k = 0; k < 16; k++) srv[tid + (k<<9)] = __ldg(&inv[tid + (k<<9)]);
    }
    // stage Acol table (1856 float4 / 512)
    {
        const float4* gv = (const float4*)g_Acol;
        float4* sv = (float4*)sAcol;
        for (int k = tid; k < NOFF*64; k += 512) sv[k] = gv[k];
    }
    // stage this block's A-row coefficients
    if (tid < NOFF) sArow[tid] = g_Arow[(tid<<7) + x];
    // stage xl-slice of pair superops
    for (int k = tid; k < NPAIR*64; k += 512) {
        int p = k >> 6;
        int mi = c_mi[p], mj = c_mj[p];
        int xl = (((x&mi)!=0)<<1)|((x&mj)!=0);
        sSx[k] = g_Sp[p][xl*64 + (k & 63)];
    }
    // stage xl-slice of single-site superops
    if (tid >= 512-NQ*8) {
        int t = tid - (512-NQ*8);
        int i = t >> 3;
        int mi = 1<<(6-i);
        int xl = (x & mi) != 0;
        sSsx[t] = g_Ss1[i][xl*8 + (t & 7)];
    }
    __syncthreads();

    float re = 0.f, im = 0.f;

    // sparse dense-part: A rho (rows) + rho A^dagger (cols), 29 offsets split by q
    {
        const float2* rowX = sRho + (x<<7);
        int k0 = c_k0[q], k1 = c_k1[q];
        for (int k = k0; k < k1; k++) {
            int d = c_d[k];
            float2 c1 = sArow[k];
            float2 r1 = sRho[((x^d)<<7) + y];
            re = fmaf(c1.x, r1.x, re); re = fmaf(-c1.y, r1.y, re);
            im = fmaf(c1.x, r1.y, im); im = fmaf( c1.y, r1.x, im);
            float2 c2 = sAcol[(k<<7) + y];
            float2 r2 = rowX[y^d];
            re = fmaf(c2.x, r2.x, re); re = fmaf(-c2.y, r2.y, re);
            im = fmaf(c2.x, r2.y, im); im = fmaf( c2.y, r2.x, im);
        }
    }

    // dissipator: pair superoperators split by q
    {
        int p0 = c_p0[q], p1 = c_p1[q];
        for (int p = p0; p < p1; p++) {
            int mi = c_mi[p], mj = c_mj[p], m = mi|mj;
            int yl = (((y&mi)!=0)<<1)|((y&mj)!=0);
            int xb = (x & ~m) << 7;
            int y0 = y & ~m;
            int xr0 = xb, xr1 = xb + (mj<<7), xr2 = xb + (mi<<7), xr3 = xb + (m<<7);
            int yc0 = y0, yc1 = y0 + mj, yc2 = y0 + mi, yc3 = y0 + m;
            const float4* Sp = reinterpret_cast<const float4*>(sSx + p*64 + yl*16);
            float4 s0 = Sp[0], s1 = Sp[1], s2 = Sp[2], s3 = Sp[3];
            float2 r;
            r = sRho[xr0+yc0]; re = fmaf(s0.x,r.x,re); im = fmaf(s0.x,r.y,im);
            r = sRho[xr0+yc1]; re = fmaf(s0.y,r.x,re); im = fmaf(s0.y,r.y,im);
            r = sRho[xr0+yc2]; re = fmaf(s0.z,r.x,re); im = fmaf(s0.z,r.y,im);
            r = sRho[xr0+yc3]; re = fmaf(s0.w,r.x,re); im = fmaf(s0.w,r.y,im);
            r = sRho[xr1+yc0]; re = fmaf(s1.x,r.x,re); im = fmaf(s1.x,r.y,im);
            r = sRho[xr1+yc1]; re = fmaf(s1.y,r.x,re); im = fmaf(s1.y,r.y,im);
            r = sRho[xr1+yc2]; re = fmaf(s1.z,r.x,re); im = fmaf(s1.z,r.y,im);
            r = sRho[xr1+yc3]; re = fmaf(s1.w,r.x,re); im = fmaf(s1.w,r.y,im);
            r = sRho[xr2+yc0]; re = fmaf(s2.x,r.x,re); im = fmaf(s2.x,r.y,im);
            r = sRho[xr2+yc1]; re = fmaf(s2.y,r.x,re); im = fmaf(s2.y,r.y,im);
            r = sRho[xr2+yc2]; re = fmaf(s2.z,r.x,re); im = fmaf(s2.z,r.y,im);
            r = sRho[xr2+yc3]; re = fmaf(s2.w,r.x,re); im = fmaf(s2.w,r.y,im);
            r = sRho[xr3+yc0]; re = fmaf(s3.x,r.x,re); im = fmaf(s3.x,r.y,im);
            r = sRho[xr3+yc1]; re = fmaf(s3.y,r.x,re); im = fmaf(s3.y,r.y,im);
            r = sRho[xr3+yc2]; re = fmaf(s3.z,r.x,re); im = fmaf(s3.z,r.y,im);
            r = sRho[xr3+yc3]; re = fmaf(s3.w,r.x,re); im = fmaf(s3.w,r.y,im);
        }
    }

    // dissipator: single-site superoperators split by q
    {
        int i0 = c_s0[q], i1 = c_s1[q];
        for (int i = i0; i < i1; i++) {
            int mi = 1<<(6-i);
            int yl = (y&mi)!=0;
            int xb = (x & ~mi) << 7;
            int y0 = y & ~mi;
            const float* Ss = sSsx + i*8 + yl*4;
            float s0 = Ss[0], s1 = Ss[1], s2 = Ss[2], s3 = Ss[3];
            float2 r;
            r = sRho[xb + y0];                re = fmaf(s0,r.x,re); im = fmaf(s0,r.y,im);
            r = sRho[xb + y0 + mi];           re = fmaf(s1,r.x,re); im = fmaf(s1,r.y,im);
            r = sRho[xb + (mi<<7) + y0];      re = fmaf(s2,r.x,re); im = fmaf(s2,r.y,im);
            r = sRho[xb + (mi<<7) + y0 + mi]; re = fmaf(s3,r.x,re); im = fmaf(s3,r.y,im);
        }
    }

    // reduce 4 partials, RK4 combine on q==0
    if (q != 0) sPart[((q-1)<<7) + y] = make_float2(re, im);
    __syncthreads();
    if (q == 0) {
        float2 p1 = sPart[y], p2 = sPart[128+y], p3 = sPart[256+y];
        re += p1.x + p2.x + p3.x;
        im += p1.y + p2.y + p3.y;
        int idx = (x<<7) + y;
        float dt = __ldg(&t_eval[step+1]) - __ldg(&t_eval[step]);
        const float2* sb = rsv(selSB);
        float2* so = rsvw(selSO);
        float cs = fs*dt;
        float2 sv = __ldg(&sb[idx]);
        float2 ov = make_float2(fmaf(cs, re, sv.x), fmaf(cs, im, sv.y));
        so[idx] = ov;
        if (writeReal) outReal[idx] = ov.x;
        if (fa != 0.f) {
            const float2* ab = rsv(selAB);
            float2 av = __ldg(&ab[idx]);
            float ca = fa*dt;
            g_acc[idx] = make_float2(fmaf(ca, re, av.x), fmaf(ca, im, av.y));
        }
    }
}

// ---------------- launcher ----------------
extern "C" void kernel_launch(void* const* d_in, const int* in_sizes, int n_in,
                              void* d_out, int out_size)
{
    const float *features=0, *t_eval=0, *W1=0, *b1=0, *W2=0, *b2=0;
    const float *Hself=0, *Hcoup=0, *rates=0, *rho0=0;
    int n784 = 0;
    for (int i = 0; i < n_in; i++) {
        const float* p = (const float*)d_in[i];
        switch (in_sizes[i]) {
            case 14:    features = p; break;
            case 5:     t_eval   = p; break;
            case 128:   W1       = p; break;
            case 64:    b1       = p; break;
            case 256:   W2       = p; break;
            case 4:     b2       = p; break;
            case 28:    Hself    = p; break;
            case 784:   if (n784++ == 0) Hcoup = p; else rates = p; break;
            case 16384: rho0     = p; break;
            default: break;
        }
    }
    if (!features) features = (const float*)d_in[0];
    if (!t_eval)   t_eval   = (const float*)d_in[1];
    if (!W1)       W1       = (const float*)d_in[2];
    if (!b1)       b1       = (const float*)d_in[3];
    if (!W2)       W2       = (const float*)d_in[4];
    if (!b2)       b2       = (const float*)d_in[5];
    if (!Hself)    Hself    = (const float*)d_in[6];
    if (!Hcoup)    Hcoup    = (const float*)d_in[7];
    if (!rates)    rates    = (const float*)d_in[8];
    if (!rho0)     rho0     = (const float*)d_in[9];

    float* out = (float*)d_out;   // float32 real output, (5,128,128)

    static int attrDone = 0;
    if (!attrDone) {
        cudaFuncSetAttribute(rhs_kernel, cudaFuncAttributeMaxDynamicSharedMemorySize, SMEM_BYTES);
        attrDone = 1;
    }

    prep_kernel<<<1, 32>>>(features, W1, b1, W2, b2, Hself, Hcoup, rates);
    build_a_kernel<<<64, 256>>>();
    build_sparse_kernel<<<(NOFF*D + 255)/256, 256>>>();
    init_kernel<<<64, 256>>>(rho0, out);

    // sel codes: 0 = g_st0, 1 = g_st1, 2 = g_acc, 3 = g_rho
    for (int t = 0; t < 4; t++) {
        float* outSlice = out + (t+1)*D*D;
        rhs_kernel<<<D, 512, SMEM_BYTES>>>(outSlice, 3, 3, 3, 0, 0, t_eval, t, 0.5f, 1.f/6.f);
        rhs_kernel<<<D, 512, SMEM_BYTES>>>(outSlice, 0, 3, 2, 1, 0, t_eval, t, 0.5f, 1.f/3.f);
        rhs_kernel<<<D, 512, SMEM_BYTES>>>(outSlice, 1, 3, 2, 0, 0, t_eval, t, 1.0f, 1.f/3.f);
        rhs_kernel<<<D, 512, SMEM_BYTES>>>(outSlice, 0, 2, 2, 3, 1, t_eval, t, 1.f/6.f, 0.f);
    }
    (void)out_size;
}

// round 8
// speedup vs baseline: 2.4571x; 1.1651x over previous
#include <cuda_runtime.h>
#include <math.h>

#define D 128
#define NQ 7
#define NPAIR 21
#define NOFF 29   // 1 + 7 + 21 sparse offsets of A / accessed-row set

// ---------------- device-side scratch (no runtime allocation) ----------------
__device__ float  g_Hs1[NQ][4];
__device__ float  g_Cs1[NQ][4];
__device__ float  g_Ss1[NQ][16];
__device__ float  g_Hp[NPAIR][16];
__device__ float  g_Cp[NPAIR][16];
__device__ float  g_Sp[NPAIR][256];
__device__ __align__(16) float2 g_Arow[NOFF*D];    // Arow[k][x] = A[x][x^d_k]
__device__ __align__(16) float2 g_Acol[NOFF*D];    // Acol[k][y] = conj(A[y][y^d_k])
__device__ __align__(16) float2 g_rho[D*D];
__device__ __align__(16) float2 g_st0[D*D];
__device__ __align__(16) float2 g_st1[D*D];
__device__ __align__(16) float2 g_acc[D*D];

__constant__ int c_pi[NPAIR] = {0,0,0,0,0,0, 1,1,1,1,1, 2,2,2,2, 3,3,3, 4,4, 5};
__constant__ int c_pj[NPAIR] = {1,2,3,4,5,6, 2,3,4,5,6, 3,4,5,6, 4,5,6, 5,6, 6};
__constant__ int c_mi[NPAIR] = {64,64,64,64,64,64, 32,32,32,32,32, 16,16,16,16, 8,8,8, 4,4, 2};
__constant__ int c_mj[NPAIR] = {32,16, 8, 4, 2, 1, 16, 8, 4, 2, 1,  8, 4, 2, 1, 4,2,1, 2,1, 1};
// sparse offsets: 0, single bits, pair masks
__constant__ int c_d[NOFF] = {0, 64,32,16,8,4,2,1,
    96,80,72,68,66,65, 48,40,36,34,33, 24,20,18,17, 12,10,9, 6,5, 3};
// offset value -> slot index (255 = unused)
__constant__ unsigned char c_lut[128] = {
    0,7,6,28,5,27,26,255,  4,25,24,255,23,255,255,255,
    3,22,21,255,20,255,255,255,  19,255,255,255,255,255,255,255,
    2,18,17,255,16,255,255,255,  15,255,255,255,255,255,255,255,
    14,255,255,255,255,255,255,255,  255,255,255,255,255,255,255,255,
    1,13,12,255,11,255,255,255,  10,255,255,255,255,255,255,255,
    9,255,255,255,255,255,255,255,  255,255,255,255,255,255,255,255,
    8,255,255,255,255,255,255,255,  255,255,255,255,255,255,255,255,
    255,255,255,255,255,255,255,255,  255,255,255,255,255,255,255,255};

// 5-way work split tables (group q = tid>>7, 640 threads)
__constant__ int c5_k0[5] = {0, 6, 12, 18, 24};
__constant__ int c5_k1[5] = {6, 12, 18, 24, 29};
__constant__ int c5_p0[5] = {0, 4, 8, 12, 16};
__constant__ int c5_p1[5] = {4, 8, 12, 16, 21};
__constant__ int c5_s0[5] = {0, 2, 4, 5, 6};
__constant__ int c5_s1[5] = {2, 4, 5, 6, 7};

// dynamic smem layout (bytes)
#define SM_RHO    0          // float2[29*128] = 29696
#define SM_ACOL   29696      // float2[29*128] = 29696
#define SM_AROW   59392      // float2[32]     = 256
#define SM_PART   59648      // float2[4*128]  = 4096
#define SM_SX     63744      // float[21*64]   = 5376
#define SM_SSX    69120      // float[7*8]     = 224
#define SMEM_BYTES 69376

// ---------------- setup: MLP + small operator algebra ----------------
__global__ void prep_kernel(const float* __restrict__ features,
                            const float* __restrict__ W1, const float* __restrict__ b1,
                            const float* __restrict__ W2, const float* __restrict__ b2,
                            const float* __restrict__ Hself, const float* __restrict__ Hcoup,
                            const float* __restrict__ rates)
{
    __shared__ float s_ops[NQ][4];
    int tid = threadIdx.x;

    if (tid < NQ) {
        float f0 = features[tid*2+0], f1 = features[tid*2+1];
        float op0 = b2[0], op1 = b2[1], op2 = b2[2], op3 = b2[3];
        for (int h = 0; h < 64; h++) {
            float t = f0*W1[h] + f1*W1[64+h] + b1[h];
            t = fmaxf(t, 0.f);
            op0 += t*W2[h*4+0]; op1 += t*W2[h*4+1];
            op2 += t*W2[h*4+2]; op3 += t*W2[h*4+3];
        }
        s_ops[tid][0]=op0; s_ops[tid][1]=op1; s_ops[tid][2]=op2; s_ops[tid][3]=op3;
    }
    __syncthreads();

    if (tid < NQ) {
        int i = tid;
        const float* Hs = Hself + i*4;
        float o0=s_ops[i][0], o1=s_ops[i][1], o2=s_ops[i][2], o3=s_ops[i][3];
        float G0 = o0*Hs[0] + o1*Hs[2];
        float G1 = o0*Hs[1] + o1*Hs[3];
        float G2 = o2*Hs[0] + o3*Hs[2];
        float G3 = o2*Hs[1] + o3*Hs[3];
        g_Hs1[i][0] = 2.f*G0; g_Hs1[i][1] = G1+G2; g_Hs1[i][2] = G2+G1; g_Hs1[i][3] = 2.f*G3;
        const float* rr = rates + (i*NQ+i)*16;
        float B[4];
        B[0] = sqrtf(fabsf(rr[0]))*o0;
        B[1] = sqrtf(fabsf(rr[1]))*o1;
        B[2] = sqrtf(fabsf(rr[4]))*o2;
        B[3] = sqrtf(fabsf(rr[5]))*o3;
        g_Cs1[i][0] = B[0]*B[0]+B[2]*B[2];
        g_Cs1[i][1] = B[0]*B[1]+B[2]*B[3];
        g_Cs1[i][2] = B[1]*B[0]+B[3]*B[2];
        g_Cs1[i][3] = B[1]*B[1]+B[3]*B[3];
        for (int a=0;a<2;a++) for (int b=0;b<2;b++)
          for (int ap=0;ap<2;ap++) for (int bp=0;bp<2;bp++)
            g_Ss1[i][((a*2+b)*2+ap)*2+bp] = B[a*2+ap]*B[b*2+bp];
    }

    if (tid < NPAIR) {
        int p = tid, i = c_pi[p], j = c_pj[p];
        float K[16], B1[16], B2[16];
        for (int u=0;u<4;u++) for (int v=0;v<4;v++) {
            float kv = s_ops[i][(u>>1)*2+(v>>1)] * s_ops[j][(u&1)*2+(v&1)];
            K[u*4+v] = kv;
            B1[u*4+v] = sqrtf(fabsf(rates[(i*NQ+j)*16 + u*4+v])) * kv;
        }
        for (int u=0;u<4;u++) for (int v=0;v<4;v++) {
            int us = ((u&1)<<1)|(u>>1), vs = ((v&1)<<1)|(v>>1);
            float kv = s_ops[j][(us>>1)*2+(vs>>1)] * s_ops[i][(us&1)*2+(vs&1)];
            B2[u*4+v] = sqrtf(fabsf(rates[(j*NQ+i)*16 + us*4+vs])) * kv;
        }
        const float* Hc = Hcoup + (i*NQ+j)*16;
        float G4[16];
        for (int u=0;u<4;u++) for (int v=0;v<4;v++) {
            float s = 0.f;
            for (int k=0;k<4;k++) s += K[u*4+k]*Hc[k*4+v];
            G4[u*4+v] = s;
        }
        for (int u=0;u<4;u++) for (int v=0;v<4;v++)
            g_Hp[p][u*4+v] = G4[u*4+v] + G4[v*4+u];
        for (int u=0;u<4;u++) for (int v=0;v<4;v++) {
            float c = 0.f;
            for (int k=0;k<4;k++) c += B1[k*4+u]*B1[k*4+v] + B2[k*4+u]*B2[k*4+v];
            g_Cp[p][u*4+v] = c;
        }
        for (int u=0;u<4;u++) for (int v=0;v<4;v++)
          for (int ap=0;ap<4;ap++) for (int bp=0;bp<4;bp++)
            g_Sp[p][((u*4+v)*4+ap)*4+bp] = B1[u*4+ap]*B1[v*4+bp] + B2[u*4+ap]*B2[v*4+bp];
    }
}

// ---------------- build A sparse tables + init rho/out0 (merged) ----------------
__global__ void build_all_kernel(const float* __restrict__ rho0, float* __restrict__ out0)
{
    int idx = blockIdx.x*blockDim.x + threadIdx.x;   // 16384 threads
    int x = idx >> 7, y = idx & 127;
    int d = x ^ y;
    float Hv = 0.f, Mv = 0.f;
    #pragma unroll
    for (int i=0;i<NQ;i++) {
        int mi = 1<<(6-i);
        if ((d & (127 ^ mi)) == 0) {
            int xl = (x>>(6-i))&1, yl = (y>>(6-i))&1;
            Hv += g_Hs1[i][xl*2+yl];
            Mv += g_Cs1[i][xl*2+yl];
        }
    }
    #pragma unroll
    for (int p=0;p<NPAIR;p++) {
        int mi = c_mi[p], mj = c_mj[p];
        if ((d & (127 ^ (mi|mj))) == 0) {
            int xl = (((x&mi)!=0)<<1)|((x&mj)!=0);
            int yl = (((y&mi)!=0)<<1)|((y&mj)!=0);
            Hv += g_Hp[p][xl*4+yl];
            Mv += g_Cp[p][xl*4+yl];
        }
    }
    int k = c_lut[d];
    if (k < NOFF) {
        g_Arow[(k<<7)+x] = make_float2(-0.5f*Mv, -Hv);   // A[x][x^d]
        g_Acol[(k<<7)+x] = make_float2(-0.5f*Mv,  Hv);   // conj(A[x][x^d])
    }
    float v = rho0[idx];
    g_rho[idx] = make_float2(v, 0.f);
    out0[idx] = v;
}

// ---------------- buffer selection ----------------
__device__ __forceinline__ const float2* rsv(int sel) {
    if (sel == 0) return g_st0;
    if (sel == 1) return g_st1;
    if (sel == 2) return g_acc;
    return g_rho;
}
__device__ __forceinline__ float2* rsvw(int sel) {
    if (sel == 0) return g_st0;
    if (sel == 1) return g_st1;
    if (sel == 2) return g_acc;
    return g_rho;
}

// ---------------- fused RHS + RK4 stage combination ----------------
__global__ void __launch_bounds__(640, 1)
rhs_kernel(float* __restrict__ outReal,
           int selIn, int selSB, int selAB, int selSO, int writeReal,
           const float* __restrict__ t_eval, int step, float fs, float fa)
{
    extern __shared__ __align__(16) char smem[];
    float2* sRho   = (float2*)(smem + SM_RHO);    // 29 rows: sRho[k*128+col] = rho[x^d_k][col]
    float2* sAcol  = (float2*)(smem + SM_ACOL);
    float2* sArow  = (float2*)(smem + SM_AROW);
    float2* sPart  = (float2*)(smem + SM_PART);
    float*  sSx    = (float*)(smem + SM_SX);
    float*  sSsx   = (float*)(smem + SM_SSX);

    const float2* in = rsv(selIn);
    int x   = blockIdx.x;
    int tid = threadIdx.x;
    int y   = tid & 127;
    int q   = tid >> 7;

    // stage 29 rows of rho (29*64 = 1856 float4)
    {
        const float4* inv = (const float4*)in;
        float4* srv = (float4*)sRho;
        for (int t = tid; t < NOFF*64; t += 640) {
            int k = t >> 6, c4 = t & 63;
            srv[t] = __ldg(&inv[((x ^ c_d[k])<<6) + c4]);
        }
    }
    // stage Acol table (1856 float4, same for all blocks)
    {
        const float4* gv = (const float4*)g_Acol;
        float4* sv = (float4*)sAcol;
        for (int t = tid; t < NOFF*64; t += 640) sv[t] = __ldg(&gv[t]);
    }
    // this block's A-row coefficients
    if (tid < NOFF) sArow[tid] = g_Arow[(tid<<7) + x];
    // xl-slice of pair superops
    for (int t = tid; t < NPAIR*64; t += 640) {
        int p = t >> 6;
        int mi = c_mi[p], mj = c_mj[p];
        int xl = (((x&mi)!=0)<<1)|((x&mj)!=0);
        sSx[t] = g_Sp[p][xl*64 + (t & 63)];
    }
    // xl-slice of single-site superops
    if (tid >= 640-NQ*8) {
        int t = tid - (640-NQ*8);
        int i = t >> 3;
        int mi = 1<<(6-i);
        int xl = (x & mi) != 0;
        sSsx[t] = g_Ss1[i][xl*8 + (t & 7)];
    }
    __syncthreads();

    float re = 0.f, im = 0.f;

    // sparse dense-part: A rho (rows, slot k) + rho A^dagger (own row, col offsets)
    {
        int k0 = c5_k0[q], k1 = c5_k1[q];
        for (int k = k0; k < k1; k++) {
            int d = c_d[k];
            float2 c1 = sArow[k];
            float2 r1 = sRho[(k<<7) + y];
            re = fmaf(c1.x, r1.x, re); re = fmaf(-c1.y, r1.y, re);
            im = fmaf(c1.x, r1.y, im); im = fmaf( c1.y, r1.x, im);
            float2 c2 = sAcol[(k<<7) + y];
            float2 r2 = sRho[y ^ d];             // slot 0 = own row x
            re = fmaf(c2.x, r2.x, re); re = fmaf(-c2.y, r2.y, re);
            im = fmaf(c2.x, r2.y, im); im = fmaf( c2.y, r2.x, im);
        }
    }

    // dissipator: pair superoperators
    {
        int p0 = c5_p0[q], p1 = c5_p1[q];
        for (int p = p0; p < p1; p++) {
            int mi = c_mi[p], mj = c_mj[p], m = mi|mj;
            int yl = (((y&mi)!=0)<<1)|((y&mj)!=0);
            int xm = x & m;
            int xr0 = ((int)c_lut[xm])    << 7;
            int xr1 = ((int)c_lut[xm^mj]) << 7;
            int xr2 = ((int)c_lut[xm^mi]) << 7;
            int xr3 = ((int)c_lut[xm^m])  << 7;
            int y0 = y & ~m;
            int yc0 = y0, yc1 = y0 + mj, yc2 = y0 + mi, yc3 = y0 + m;
            const float4* Sp = reinterpret_cast<const float4*>(sSx + p*64 + yl*16);
            float4 s0 = Sp[0], s1 = Sp[1], s2 = Sp[2], s3 = Sp[3];
            float2 r;
            r = sRho[xr0+yc0]; re = fmaf(s0.x,r.x,re); im = fmaf(s0.x,r.y,im);
            r = sRho[xr0+yc1]; re = fmaf(s0.y,r.x,re); im = fmaf(s0.y,r.y,im);
            r = sRho[xr0+yc2]; re = fmaf(s0.z,r.x,re); im = fmaf(s0.z,r.y,im);
            r = sRho[xr0+yc3]; re = fmaf(s0.w,r.x,re); im = fmaf(s0.w,r.y,im);
            r = sRho[xr1+yc0]; re = fmaf(s1.x,r.x,re); im = fmaf(s1.x,r.y,im);
            r = sRho[xr1+yc1]; re = fmaf(s1.y,r.x,re); im = fmaf(s1.y,r.y,im);
            r = sRho[xr1+yc2]; re = fmaf(s1.z,r.x,re); im = fmaf(s1.z,r.y,im);
            r = sRho[xr1+yc3]; re = fmaf(s1.w,r.x,re); im = fmaf(s1.w,r.y,im);
            r = sRho[xr2+yc0]; re = fmaf(s2.x,r.x,re); im = fmaf(s2.x,r.y,im);
            r = sRho[xr2+yc1]; re = fmaf(s2.y,r.x,re); im = fmaf(s2.y,r.y,im);
            r = sRho[xr2+yc2]; re = fmaf(s2.z,r.x,re); im = fmaf(s2.z,r.y,im);
            r = sRho[xr2+yc3]; re = fmaf(s2.w,r.x,re); im = fmaf(s2.w,r.y,im);
            r = sRho[xr3+yc0]; re = fmaf(s3.x,r.x,re); im = fmaf(s3.x,r.y,im);
            r = sRho[xr3+yc1]; re = fmaf(s3.y,r.x,re); im = fmaf(s3.y,r.y,im);
            r = sRho[xr3+yc2]; re = fmaf(s3.z,r.x,re); im = fmaf(s3.z,r.y,im);
            r = sRho[xr3+yc3]; re = fmaf(s3.w,r.x,re); im = fmaf(s3.w,r.y,im);
        }
    }

    // dissipator: single-site superoperators
    {
        int i0 = c5_s0[q], i1 = c5_s1[q];
        for (int i = i0; i < i1; i++) {
            int mi = 1<<(6-i);
            int yl = (y&mi)!=0;
            int xmi = x & mi;
            int xb0 = ((int)c_lut[xmi])     << 7;
            int xb1 = ((int)c_lut[xmi^mi])  << 7;
            int y0 = y & ~mi;
            const float* Ss = sSsx + i*8 + yl*4;
            float s0 = Ss[0], s1 = Ss[1], s2 = Ss[2], s3 = Ss[3];
            float2 r;
            r = sRho[xb0 + y0];      re = fmaf(s0,r.x,re); im = fmaf(s0,r.y,im);
            r = sRho[xb0 + y0 + mi]; re = fmaf(s1,r.x,re); im = fmaf(s1,r.y,im);
            r = sRho[xb1 + y0];      re = fmaf(s2,r.x,re); im = fmaf(s2,r.y,im);
            r = sRho[xb1 + y0 + mi]; re = fmaf(s3,r.x,re); im = fmaf(s3,r.y,im);
        }
    }

    // reduce 5 partials, RK4 combine on q==0
    if (q != 0) sPart[((q-1)<<7) + y] = make_float2(re, im);
    __syncthreads();
    if (q == 0) {
        float2 p1 = sPart[y], p2 = sPart[128+y], p3 = sPart[256+y], p4 = sPart[384+y];
        re += p1.x + p2.x + p3.x + p4.x;
        im += p1.y + p2.y + p3.y + p4.y;
        int idx = (x<<7) + y;
        float dt = __ldg(&t_eval[step+1]) - __ldg(&t_eval[step]);
        const float2* sb = rsv(selSB);
        float2* so = rsvw(selSO);
        float cs = fs*dt;
        float2 sv = __ldg(&sb[idx]);
        float2 ov = make_float2(fmaf(cs, re, sv.x), fmaf(cs, im, sv.y));
        so[idx] = ov;
        if (writeReal) outReal[idx] = ov.x;
        if (fa != 0.f) {
            const float2* ab = rsv(selAB);
            float2 av = __ldg(&ab[idx]);
            float ca = fa*dt;
            g_acc[idx] = make_float2(fmaf(ca, re, av.x), fmaf(ca, im, av.y));
        }
    }
}

// ---------------- launcher ----------------
extern "C" void kernel_launch(void* const* d_in, const int* in_sizes, int n_in,
                              void* d_out, int out_size)
{
    const float *features=0, *t_eval=0, *W1=0, *b1=0, *W2=0, *b2=0;
    const float *Hself=0, *Hcoup=0, *rates=0, *rho0=0;
    int n784 = 0;
    for (int i = 0; i < n_in; i++) {
        const float* p = (const float*)d_in[i];
        switch (in_sizes[i]) {
            case 14:    features = p; break;
            case 5:     t_eval   = p; break;
            case 128:   W1       = p; break;
            case 64:    b1       = p; break;
            case 256:   W2       = p; break;
            case 4:     b2       = p; break;
            case 28:    Hself    = p; break;
            case 784:   if (n784++ == 0) Hcoup = p; else rates = p; break;
            case 16384: rho0     = p; break;
            default: break;
        }
    }
    if (!features) features = (const float*)d_in[0];
    if (!t_eval)   t_eval   = (const float*)d_in[1];
    if (!W1)       W1       = (const float*)d_in[2];
    if (!b1)       b1       = (const float*)d_in[3];
    if (!W2)       W2       = (const float*)d_in[4];
    if (!b2)       b2       = (const float*)d_in[5];
    if (!Hself)    Hself    = (const float*)d_in[6];
    if (!Hcoup)    Hcoup    = (const float*)d_in[7];
    if (!rates)    rates    = (const float*)d_in[8];
    if (!rho0)     rho0     = (const float*)d_in[9];

    float* out = (float*)d_out;   // float32 real output, (5,128,128)

    static int attrDone = 0;
    if (!attrDone) {
        cudaFuncSetAttribute(rhs_kernel, cudaFuncAttributeMaxDynamicSharedMemorySize, SMEM_BYTES);
        attrDone = 1;
    }

    prep_kernel<<<1, 32>>>(features, W1, b1, W2, b2, Hself, Hcoup, rates);
    build_all_kernel<<<64, 256>>>(rho0, out);

    // sel codes: 0 = g_st0, 1 = g_st1, 2 = g_acc, 3 = g_rho
    for (int t = 0; t < 4; t++) {
        float* outSlice = out + (t+1)*D*D;
        rhs_kernel<<<D, 640, SMEM_BYTES>>>(outSlice, 3, 3, 3, 0, 0, t_eval, t, 0.5f, 1.f/6.f);
        rhs_kernel<<<D, 640, SMEM_BYTES>>>(outSlice, 0, 3, 2, 1, 0, t_eval, t, 0.5f, 1.f/3.f);
        rhs_kernel<<<D, 640, SMEM_BYTES>>>(outSlice, 1, 3, 2, 0, 0, t_eval, t, 1.0f, 1.f/3.f);
        rhs_kernel<<<D, 640, SMEM_BYTES>>>(outSlice, 0, 2, 2, 3, 1, t_eval, t, 1.f/6.f, 0.f);
    }
    (void)out_size;
}

// round 9
// speedup vs baseline: 2.6595x; 1.0824x over previous
#include <cuda_runtime.h>
#include <math.h>

#define D 128
#define NQ 7
#define NPAIR 21
#define NOFF 29   // 1 + 7 + 21 sparse offsets of A / accessed-row set
#define NSTAGE 16

// ---------------- device-side scratch (no runtime allocation) ----------------
__device__ float  g_Hs1[NQ][4];
__device__ float  g_Cs1[NQ][4];
__device__ float  g_Ss1[NQ][16];
__device__ float  g_Hp[NPAIR][16];
__device__ float  g_Cp[NPAIR][16];
__device__ float  g_Sp[NPAIR][256];
__device__ __align__(16) float2 g_Arow[NOFF*D];    // Arow[k][x] = A[x][x^d_k]
__device__ __align__(16) float2 g_Acol[NOFF*D];    // Acol[k][y] = conj(A[y][y^d_k])
__device__ __align__(16) float2 g_rho[D*D];
__device__ __align__(16) float2 g_st0[D*D];
__device__ __align__(16) float2 g_st1[D*D];
__device__ __align__(16) float2 g_acc[D*D];

// software grid barrier state (self-resetting; sense ends at 0 after even # barriers)
__device__ unsigned int g_bar_count = 0;
__device__ volatile unsigned int g_bar_sense = 0;

__constant__ int c_pi[NPAIR] = {0,0,0,0,0,0, 1,1,1,1,1, 2,2,2,2, 3,3,3, 4,4, 5};
__constant__ int c_pj[NPAIR] = {1,2,3,4,5,6, 2,3,4,5,6, 3,4,5,6, 4,5,6, 5,6, 6};
__constant__ int c_mi[NPAIR] = {64,64,64,64,64,64, 32,32,32,32,32, 16,16,16,16, 8,8,8, 4,4, 2};
__constant__ int c_mj[NPAIR] = {32,16, 8, 4, 2, 1, 16, 8, 4, 2, 1,  8, 4, 2, 1, 4,2,1, 2,1, 1};
// sparse offsets: 0, single bits, pair masks
__constant__ int c_d[NOFF] = {0, 64,32,16,8,4,2,1,
    96,80,72,68,66,65, 48,40,36,34,33, 24,20,18,17, 12,10,9, 6,5, 3};
// offset value -> slot index (255 = unused)
__constant__ unsigned char c_lut[128] = {
    0,7,6,28,5,27,26,255,  4,25,24,255,23,255,255,255,
    3,22,21,255,20,255,255,255,  19,255,255,255,255,255,255,255,
    2,18,17,255,16,255,255,255,  15,255,255,255,255,255,255,255,
    14,255,255,255,255,255,255,255,  255,255,255,255,255,255,255,255,
    1,13,12,255,11,255,255,255,  10,255,255,255,255,255,255,255,
    9,255,255,255,255,255,255,255,  255,255,255,255,255,255,255,255,
    8,255,255,255,255,255,255,255,  255,255,255,255,255,255,255,255,
    255,255,255,255,255,255,255,255,  255,255,255,255,255,255,255,255};

// 5-way work split tables (group q = tid>>7, 640 threads)
__constant__ int c5_k0[5] = {0, 6, 12, 18, 24};
__constant__ int c5_k1[5] = {6, 12, 18, 24, 29};
__constant__ int c5_p0[5] = {0, 4, 8, 12, 16};
__constant__ int c5_p1[5] = {4, 8, 12, 16, 21};
__constant__ int c5_s0[5] = {0, 2, 4, 5, 6};
__constant__ int c5_s1[5] = {2, 4, 5, 6, 7};

// RK4 stage schedule: s = 4t+j.  sel codes: 0=st0, 1=st1, 2=acc, 3=rho
__constant__ int   cs_in[4] = {3, 0, 1, 0};
__constant__ int   cs_sb[4] = {3, 3, 3, 2};
__constant__ int   cs_ab[4] = {3, 2, 2, 2};
__constant__ int   cs_so[4] = {0, 1, 0, 3};
__constant__ float cs_fs[4] = {0.5f, 0.5f, 1.0f, 1.f/6.f};
__constant__ float cs_fa[4] = {1.f/6.f, 1.f/3.f, 1.f/3.f, 0.f};

// dynamic smem layout (bytes)
#define SM_RHO    0          // float2[29*128] = 29696
#define SM_ACOL   29696      // float2[29*128] = 29696
#define SM_AROW   59392      // float2[32]     = 256
#define SM_PART   59648      // float2[4*128]  = 4096
#define SM_SX     63744      // float[21*64]   = 5376
#define SM_SSX    69120      // float[7*8]     = 224
#define SMEM_BYTES 69376

// ---------------- setup: MLP + small operator algebra ----------------
__global__ void prep_kernel(const float* __restrict__ features,
                            const float* __restrict__ W1, const float* __restrict__ b1,
                            const float* __restrict__ W2, const float* __restrict__ b2,
                            const float* __restrict__ Hself, const float* __restrict__ Hcoup,
                            const float* __restrict__ rates)
{
    __shared__ float s_ops[NQ][4];
    int tid = threadIdx.x;

    if (tid < NQ) {
        float f0 = features[tid*2+0], f1 = features[tid*2+1];
        float op0 = b2[0], op1 = b2[1], op2 = b2[2], op3 = b2[3];
        for (int h = 0; h < 64; h++) {
            float t = f0*W1[h] + f1*W1[64+h] + b1[h];
            t = fmaxf(t, 0.f);
            op0 += t*W2[h*4+0]; op1 += t*W2[h*4+1];
            op2 += t*W2[h*4+2]; op3 += t*W2[h*4+3];
        }
        s_ops[tid][0]=op0; s_ops[tid][1]=op1; s_ops[tid][2]=op2; s_ops[tid][3]=op3;
    }
    __syncthreads();

    if (tid < NQ) {
        int i = tid;
        const float* Hs = Hself + i*4;
        float o0=s_ops[i][0], o1=s_ops[i][1], o2=s_ops[i][2], o3=s_ops[i][3];
        float G0 = o0*Hs[0] + o1*Hs[2];
        float G1 = o0*Hs[1] + o1*Hs[3];
        float G2 = o2*Hs[0] + o3*Hs[2];
        float G3 = o2*Hs[1] + o3*Hs[3];
        g_Hs1[i][0] = 2.f*G0; g_Hs1[i][1] = G1+G2; g_Hs1[i][2] = G2+G1; g_Hs1[i][3] = 2.f*G3;
        const float* rr = rates + (i*NQ+i)*16;
        float B[4];
        B[0] = sqrtf(fabsf(rr[0]))*o0;
        B[1] = sqrtf(fabsf(rr[1]))*o1;
        B[2] = sqrtf(fabsf(rr[4]))*o2;
        B[3] = sqrtf(fabsf(rr[5]))*o3;
        g_Cs1[i][0] = B[0]*B[0]+B[2]*B[2];
        g_Cs1[i][1] = B[0]*B[1]+B[2]*B[3];
        g_Cs1[i][2] = B[1]*B[0]+B[3]*B[2];
        g_Cs1[i][3] = B[1]*B[1]+B[3]*B[3];
        for (int a=0;a<2;a++) for (int b=0;b<2;b++)
          for (int ap=0;ap<2;ap++) for (int bp=0;bp<2;bp++)
            g_Ss1[i][((a*2+b)*2+ap)*2+bp] = B[a*2+ap]*B[b*2+bp];
    }

    if (tid < NPAIR) {
        int p = tid, i = c_pi[p], j = c_pj[p];
        float K[16], B1[16], B2[16];
        for (int u=0;u<4;u++) for (int v=0;v<4;v++) {
            float kv = s_ops[i][(u>>1)*2+(v>>1)] * s_ops[j][(u&1)*2+(v&1)];
            K[u*4+v] = kv;
            B1[u*4+v] = sqrtf(fabsf(rates[(i*NQ+j)*16 + u*4+v])) * kv;
        }
        for (int u=0;u<4;u++) for (int v=0;v<4;v++) {
            int us = ((u&1)<<1)|(u>>1), vs = ((v&1)<<1)|(v>>1);
            float kv = s_ops[j][(us>>1)*2+(vs>>1)] * s_ops[i][(us&1)*2+(vs&1)];
            B2[u*4+v] = sqrtf(fabsf(rates[(j*NQ+i)*16 + us*4+vs])) * kv;
        }
        const float* Hc = Hcoup + (i*NQ+j)*16;
        float G4[16];
        for (int u=0;u<4;u++) for (int v=0;v<4;v++) {
            float s = 0.f;
            for (int k=0;k<4;k++) s += K[u*4+k]*Hc[k*4+v];
            G4[u*4+v] = s;
        }
        for (int u=0;u<4;u++) for (int v=0;v<4;v++)
            g_Hp[p][u*4+v] = G4[u*4+v] + G4[v*4+u];
        for (int u=0;u<4;u++) for (int v=0;v<4;v++) {
            float c = 0.f;
            for (int k=0;k<4;k++) c += B1[k*4+u]*B1[k*4+v] + B2[k*4+u]*B2[k*4+v];
            g_Cp[p][u*4+v] = c;
        }
        for (int u=0;u<4;u++) for (int v=0;v<4;v++)
          for (int ap=0;ap<4;ap++) for (int bp=0;bp<4;bp++)
            g_Sp[p][((u*4+v)*4+ap)*4+bp] = B1[u*4+ap]*B1[v*4+bp] + B2[u*4+ap]*B2[v*4+bp];
    }
}

// ---------------- build A sparse tables + init rho/out0 (merged) ----------------
__global__ void build_all_kernel(const float* __restrict__ rho0, float* __restrict__ out0)
{
    int idx = blockIdx.x*blockDim.x + threadIdx.x;   // 16384 threads
    int x = idx >> 7, y = idx & 127;
    int d = x ^ y;
    float Hv = 0.f, Mv = 0.f;
    #pragma unroll
    for (int i=0;i<NQ;i++) {
        int mi = 1<<(6-i);
        if ((d & (127 ^ mi)) == 0) {
            int xl = (x>>(6-i))&1, yl = (y>>(6-i))&1;
            Hv += g_Hs1[i][xl*2+yl];
            Mv += g_Cs1[i][xl*2+yl];
        }
    }
    #pragma unroll
    for (int p=0;p<NPAIR;p++) {
        int mi = c_mi[p], mj = c_mj[p];
        if ((d & (127 ^ (mi|mj))) == 0) {
            int xl = (((x&mi)!=0)<<1)|((x&mj)!=0);
            int yl = (((y&mi)!=0)<<1)|((y&mj)!=0);
            Hv += g_Hp[p][xl*4+yl];
            Mv += g_Cp[p][xl*4+yl];
        }
    }
    int k = c_lut[d];
    if (k < NOFF) {
        g_Arow[(k<<7)+x] = make_float2(-0.5f*Mv, -Hv);   // A[x][x^d]
        g_Acol[(k<<7)+x] = make_float2(-0.5f*Mv,  Hv);   // conj(A[x][x^d])
    }
    float v = rho0[idx];
    g_rho[idx] = make_float2(v, 0.f);
    out0[idx] = v;
}

// ---------------- buffer selection ----------------
__device__ __forceinline__ const float2* rsv(int sel) {
    if (sel == 0) return g_st0;
    if (sel == 1) return g_st1;
    if (sel == 2) return g_acc;
    return g_rho;
}
__device__ __forceinline__ float2* rsvw(int sel) {
    if (sel == 0) return g_st0;
    if (sel == 1) return g_st1;
    if (sel == 2) return g_acc;
    return g_rho;
}

// ---------------- software grid barrier (all blocks co-resident) ----------------
__device__ __forceinline__ void grid_barrier(unsigned int &sense)
{
    __threadfence();            // make this thread's stage writes visible at L2
    __syncthreads();            // all threads in block fenced + done
    if (threadIdx.x == 0) {
        sense ^= 1u;
        unsigned int a = atomicAdd(&g_bar_count, 1u);
        if (a == gridDim.x - 1) {
            g_bar_count = 0;    // reset before releasing (no one can re-arrive yet)
            __threadfence();
            g_bar_sense = sense;
        } else {
            while (g_bar_sense != sense) { }
        }
    }
    __syncthreads();
}

// ---------------- persistent solver: all 16 RK4 stages in one kernel ----------------
__global__ void __launch_bounds__(640, 1)
solve_kernel(float* __restrict__ out, const float* __restrict__ t_eval)
{
    extern __shared__ __align__(16) char smem[];
    float2* sRho   = (float2*)(smem + SM_RHO);    // 29 rows: sRho[k*128+col] = in[x^d_k][col]
    float2* sAcol  = (float2*)(smem + SM_ACOL);
    float2* sArow  = (float2*)(smem + SM_AROW);
    float2* sPart  = (float2*)(smem + SM_PART);
    float*  sSx    = (float*)(smem + SM_SX);
    float*  sSsx   = (float*)(smem + SM_SSX);

    int x   = blockIdx.x;
    int tid = threadIdx.x;
    int y   = tid & 127;
    int q   = tid >> 7;

    // ---- stage invariant tables ONCE ----
    {
        const float4* gv = (const float4*)g_Acol;
        float4* sv = (float4*)sAcol;
        for (int t = tid; t < NOFF*64; t += 640) sv[t] = __ldg(&gv[t]);
    }
    if (tid < NOFF) sArow[tid] = g_Arow[(tid<<7) + x];
    for (int t = tid; t < NPAIR*64; t += 640) {
        int p = t >> 6;
        int mi = c_mi[p], mj = c_mj[p];
        int xl = (((x&mi)!=0)<<1)|((x&mj)!=0);
        sSx[t] = g_Sp[p][xl*64 + (t & 63)];
    }
    if (tid >= 640-NQ*8) {
        int t = tid - (640-NQ*8);
        int i = t >> 3;
        int mi = 1<<(6-i);
        int xl = (x & mi) != 0;
        sSsx[t] = g_Ss1[i][xl*8 + (t & 7)];
    }

    unsigned int sense = 0;

    for (int s = 0; s < NSTAGE; s++) {
        int j = s & 3, step = s >> 2;
        const float2* in = rsv(cs_in[j]);

        // stage 29 rows of current input (L2-coherent loads: written by other blocks)
        {
            const float4* inv = (const float4*)in;
            float4* srv = (float4*)sRho;
            for (int t = tid; t < NOFF*64; t += 640) {
                int k = t >> 6, c4 = t & 63;
                srv[t] = __ldcg(&inv[((x ^ c_d[k])<<6) + c4]);
            }
        }
        __syncthreads();

        float re = 0.f, im = 0.f;

        // sparse dense-part: A rho (rows) + rho A^dagger (own row, col offsets)
        {
            int k0 = c5_k0[q], k1 = c5_k1[q];
            for (int k = k0; k < k1; k++) {
                int d = c_d[k];
                float2 c1 = sArow[k];
                float2 r1 = sRho[(k<<7) + y];
                re = fmaf(c1.x, r1.x, re); re = fmaf(-c1.y, r1.y, re);
                im = fmaf(c1.x, r1.y, im); im = fmaf( c1.y, r1.x, im);
                float2 c2 = sAcol[(k<<7) + y];
                float2 r2 = sRho[y ^ d];             // slot 0 = own row x
                re = fmaf(c2.x, r2.x, re); re = fmaf(-c2.y, r2.y, re);
                im = fmaf(c2.x, r2.y, im); im = fmaf( c2.y, r2.x, im);
            }
        }

        // dissipator: pair superoperators
        {
            int p0 = c5_p0[q], p1 = c5_p1[q];
            for (int p = p0; p < p1; p++) {
                int mi = c_mi[p], mj = c_mj[p], m = mi|mj;
                int yl = (((y&mi)!=0)<<1)|((y&mj)!=0);
                int xm = x & m;
                int xr0 = ((int)c_lut[xm])    << 7;
                int xr1 = ((int)c_lut[xm^mj]) << 7;
                int xr2 = ((int)c_lut[xm^mi]) << 7;
                int xr3 = ((int)c_lut[xm^m])  << 7;
                int y0 = y & ~m;
                int yc0 = y0, yc1 = y0 + mj, yc2 = y0 + mi, yc3 = y0 + m;
                const float4* Sp = reinterpret_cast<const float4*>(sSx + p*64 + yl*16);
                float4 s0 = Sp[0], s1 = Sp[1], s2 = Sp[2], s3 = Sp[3];
                float2 r;
                r = sRho[xr0+yc0]; re = fmaf(s0.x,r.x,re); im = fmaf(s0.x,r.y,im);
                r = sRho[xr0+yc1]; re = fmaf(s0.y,r.x,re); im = fmaf(s0.y,r.y,im);
                r = sRho[xr0+yc2]; re = fmaf(s0.z,r.x,re); im = fmaf(s0.z,r.y,im);
                r = sRho[xr0+yc3]; re = fmaf(s0.w,r.x,re); im = fmaf(s0.w,r.y,im);
                r = sRho[xr1+yc0]; re = fmaf(s1.x,r.x,re); im = fmaf(s1.x,r.y,im);
                r = sRho[xr1+yc1]; re = fmaf(s1.y,r.x,re); im = fmaf(s1.y,r.y,im);
                r = sRho[xr1+yc2]; re = fmaf(s1.z,r.x,re); im = fmaf(s1.z,r.y,im);
                r = sRho[xr1+yc3]; re = fmaf(s1.w,r.x,re); im = fmaf(s1.w,r.y,im);
                r = sRho[xr2+yc0]; re = fmaf(s2.x,r.x,re); im = fmaf(s2.x,r.y,im);
                r = sRho[xr2+yc1]; re = fmaf(s2.y,r.x,re); im = fmaf(s2.y,r.y,im);
                r = sRho[xr2+yc2]; re = fmaf(s2.z,r.x,re); im = fmaf(s2.z,r.y,im);
                r = sRho[xr2+yc3]; re = fmaf(s2.w,r.x,re); im = fmaf(s2.w,r.y,im);
                r = sRho[xr3+yc0]; re = fmaf(s3.x,r.x,re); im = fmaf(s3.x,r.y,im);
                r = sRho[xr3+yc1]; re = fmaf(s3.y,r.x,re); im = fmaf(s3.y,r.y,im);
                r = sRho[xr3+yc2]; re = fmaf(s3.z,r.x,re); im = fmaf(s3.z,r.y,im);
                r = sRho[xr3+yc3]; re = fmaf(s3.w,r.x,re); im = fmaf(s3.w,r.y,im);
            }
        }

        // dissipator: single-site superoperators
        {
            int i0 = c5_s0[q], i1 = c5_s1[q];
            for (int i = i0; i < i1; i++) {
                int mi = 1<<(6-i);
                int yl = (y&mi)!=0;
                int xmi = x & mi;
                int xb0 = ((int)c_lut[xmi])     << 7;
                int xb1 = ((int)c_lut[xmi^mi])  << 7;
                int y0 = y & ~mi;
                const float* Ss = sSsx + i*8 + yl*4;
                float s0 = Ss[0], s1 = Ss[1], s2 = Ss[2], s3 = Ss[3];
                float2 r;
                r = sRho[xb0 + y0];      re = fmaf(s0,r.x,re); im = fmaf(s0,r.y,im);
                r = sRho[xb0 + y0 + mi]; re = fmaf(s1,r.x,re); im = fmaf(s1,r.y,im);
                r = sRho[xb1 + y0];      re = fmaf(s2,r.x,re); im = fmaf(s2,r.y,im);
                r = sRho[xb1 + y0 + mi]; re = fmaf(s3,r.x,re); im = fmaf(s3,r.y,im);
            }
        }

        // reduce 5 partials, RK4 combine on q==0
        if (q != 0) sPart[((q-1)<<7) + y] = make_float2(re, im);
        __syncthreads();
        if (q == 0) {
            float2 p1 = sPart[y], p2 = sPart[128+y], p3 = sPart[256+y], p4 = sPart[384+y];
            re += p1.x + p2.x + p3.x + p4.x;
            im += p1.y + p2.y + p3.y + p4.y;
            int idx = (x<<7) + y;
            float dt = __ldg(&t_eval[step+1]) - __ldg(&t_eval[step]);
            const float2* sb = rsv(cs_sb[j]);
            float2* so = rsvw(cs_so[j]);
            float cs = cs_fs[j]*dt;
            float2 sv = __ldcg(&sb[idx]);
            float2 ov = make_float2(fmaf(cs, re, sv.x), fmaf(cs, im, sv.y));
            so[idx] = ov;
            if (j == 3) out[(step+1)*D*D + idx] = ov.x;
            float fa = cs_fa[j];
            if (fa != 0.f) {
                const float2* ab = rsv(cs_ab[j]);
                float2 av = __ldcg(&ab[idx]);
                float ca = fa*dt;
                g_acc[idx] = make_float2(fmaf(ca, re, av.x), fmaf(ca, im, av.y));
            }
        }

        grid_barrier(sense);   // 16 per launch (even) -> sense ends at 0, replay-safe
    }
}

// ---------------- launcher ----------------
extern "C" void kernel_launch(void* const* d_in, const int* in_sizes, int n_in,
                              void* d_out, int out_size)
{
    const float *features=0, *t_eval=0, *W1=0, *b1=0, *W2=0, *b2=0;
    const float *Hself=0, *Hcoup=0, *rates=0, *rho0=0;
    int n784 = 0;
    for (int i = 0; i < n_in; i++) {
        const float* p = (const float*)d_in[i];
        switch (in_sizes[i]) {
            case 14:    features = p; break;
            case 5:     t_eval   = p; break;
            case 128:   W1       = p; break;
            case 64:    b1       = p; break;
            case 256:   W2       = p; break;
            case 4:     b2       = p; break;
            case 28:    Hself    = p; break;
            case 784:   if (n784++ == 0) Hcoup = p; else rates = p; break;
            case 16384: rho0     = p; break;
            default: break;
        }
    }
    if (!features) features = (const float*)d_in[0];
    if (!t_eval)   t_eval   = (const float*)d_in[1];
    if (!W1)       W1       = (const float*)d_in[2];
    if (!b1)       b1       = (const float*)d_in[3];
    if (!W2)       W2       = (const float*)d_in[4];
    if (!b2)       b2       = (const float*)d_in[5];
    if (!Hself)    Hself    = (const float*)d_in[6];
    if (!Hcoup)    Hcoup    = (const float*)d_in[7];
    if (!rates)    rates    = (const float*)d_in[8];
    if (!rho0)     rho0     = (const float*)d_in[9];

    float* out = (float*)d_out;   // float32 real output, (5,128,128)

    static int attrDone = 0;
    if (!attrDone) {
        cudaFuncSetAttribute(solve_kernel, cudaFuncAttributeMaxDynamicSharedMemorySize, SMEM_BYTES);
        attrDone = 1;
    }

    prep_kernel<<<1, 32>>>(features, W1, b1, W2, b2, Hself, Hcoup, rates);
    build_all_kernel<<<64, 256>>>(rho0, out);
    solve_kernel<<<D, 640, SMEM_BYTES>>>(out, t_eval);
    (void)out_size;
}

// round 11
// speedup vs baseline: 3.0930x; 1.1630x over previous
#include <cuda_runtime.h>
#include <math.h>

#define D 128
#define NQ 7
#define NPAIR 21
#define NOFF 29   // 1 + 7 + 21 sparse offsets of A / accessed-row set
#define NSTAGE 16
#define NTHR 640

// ---------------- device-side scratch (no runtime allocation) ----------------
__device__ float  g_Hs1[NQ][4];
__device__ float  g_Cs1[NQ][4];
__device__ float  g_Ss1[NQ][16];
__device__ float  g_Hp[NPAIR][16];
__device__ float  g_Cp[NPAIR][16];
__device__ float  g_Sp[NPAIR][256];
__device__ __align__(16) float2 g_Arow[NOFF*D];    // Arow[k][x] = A[x][x^d_k]
__device__ __align__(16) float2 g_Acol[NOFF*D];    // Acol[k][y] = conj(A[y][y^d_k])
__device__ __align__(16) float2 g_rho[D*D];
__device__ __align__(16) float2 g_st0[D*D];
__device__ __align__(16) float2 g_st1[D*D];
__device__ __align__(16) float2 g_acc[D*D];

// software grid barrier state (18 barriers/launch = even -> sense ends at 0, replay-safe)
__device__ unsigned int g_bar_count = 0;
__device__ volatile unsigned int g_bar_sense = 0;

// runtime-indexed tables (constant memory)
__constant__ int c_pi[NPAIR] = {0,0,0,0,0,0, 1,1,1,1,1, 2,2,2,2, 3,3,3, 4,4, 5};
__constant__ int c_pj[NPAIR] = {1,2,3,4,5,6, 2,3,4,5,6, 3,4,5,6, 4,5,6, 5,6, 6};
__constant__ int c_mi[NPAIR] = {64,64,64,64,64,64, 32,32,32,32,32, 16,16,16,16, 8,8,8, 4,4, 2};
__constant__ int c_mj[NPAIR] = {32,16, 8, 4, 2, 1, 16, 8, 4, 2, 1,  8, 4, 2, 1, 4,2,1, 2,1, 1};
__constant__ int c_dd[NOFF]  = {0, 64,32,16,8,4,2,1,
    96,80,72,68,66,65, 48,40,36,34,33, 24,20,18,17, 12,10,9, 6,5, 3};
// offset value -> slot index (255 = unused)
__constant__ unsigned char c_lut[128] = {
    0,7,6,28,5,27,26,255,  4,25,24,255,23,255,255,255,
    3,22,21,255,20,255,255,255,  19,255,255,255,255,255,255,255,
    2,18,17,255,16,255,255,255,  15,255,255,255,255,255,255,255,
    14,255,255,255,255,255,255,255,  255,255,255,255,255,255,255,255,
    1,13,12,255,11,255,255,255,  10,255,255,255,255,255,255,255,
    9,255,255,255,255,255,255,255,  255,255,255,255,255,255,255,255,
    8,255,255,255,255,255,255,255,  255,255,255,255,255,255,255,255,
    255,255,255,255,255,255,255,255,  255,255,255,255,255,255,255,255};

// RK4 stage schedule: s = 4t+j.  sel codes: 0=st0, 1=st1, 2=acc, 3=rho
__constant__ int   cs_in[4] = {3, 0, 1, 0};
__constant__ int   cs_sb[4] = {3, 3, 3, 2};
__constant__ int   cs_ab[4] = {3, 2, 2, 2};
__constant__ int   cs_so[4] = {0, 1, 0, 3};
__constant__ float cs_fs[4] = {0.5f, 0.5f, 1.0f, 1.f/6.f};
__constant__ float cs_fa[4] = {1.f/6.f, 1.f/3.f, 1.f/3.f, 0.f};

// compile-time tables: constexpr device functions (fold to immediates in unrolled loops)
#define DCE __host__ __device__ __forceinline__ constexpr
DCE int ct_mi(int p) { const int v[NPAIR] = {64,64,64,64,64,64, 32,32,32,32,32, 16,16,16,16, 8,8,8, 4,4, 2}; return v[p]; }
DCE int ct_mj(int p) { const int v[NPAIR] = {32,16, 8, 4, 2, 1, 16, 8, 4, 2, 1,  8, 4, 2, 1, 4,2,1, 2,1, 1}; return v[p]; }
DCE int ct_dd(int k) { const int v[NOFF]  = {0, 64,32,16,8,4,2,1,
    96,80,72,68,66,65, 48,40,36,34,33, 24,20,18,17, 12,10,9, 6,5, 3}; return v[k]; }
DCE int ct_k0(int q) { const int v[5] = {0, 6, 12, 18, 24}; return v[q]; }
DCE int ct_k1(int q) { const int v[5] = {6, 12, 18, 24, 29}; return v[q]; }
DCE int ct_p0(int q) { const int v[5] = {0, 4, 8, 12, 16}; return v[q]; }
DCE int ct_p1(int q) { const int v[5] = {4, 8, 12, 16, 21}; return v[q]; }
DCE int ct_s0(int q) { const int v[5] = {0, 2, 4, 5, 6}; return v[q]; }
DCE int ct_s1(int q) { const int v[5] = {2, 4, 5, 6, 7}; return v[q]; }
DCE int ct_sb(int i) { const int v[NQ] = {64,32,16,8,4,2,1}; return v[i]; }

// dynamic smem layout (bytes)
#define SM_RHO    0          // float2[29*128] = 29696  (also prep scratch)
#define SM_ACOL   29696      // float2[29*128] = 29696
#define SM_AROW   59392      // float2[32]     = 256
#define SM_PART   59648      // float2[4*128]  = 4096
#define SM_SX     63744      // float[21*64]   = 5376
#define SM_SSX    69120      // float[7*8]     = 224
#define SMEM_BYTES 69376
// prep scratch overlay (inside SM_RHO region, used only before rho staged)
#define PR_OPS    0          // float[28]
#define PR_K      128        // float[336]
#define PR_B1     1472       // float[336]
#define PR_B2     2816       // float[336]

// ---------------- buffer selection ----------------
__device__ __forceinline__ const float2* rsv(int sel) {
    if (sel == 0) return g_st0;
    if (sel == 1) return g_st1;
    if (sel == 2) return g_acc;
    return g_rho;
}
__device__ __forceinline__ float2* rsvw(int sel) {
    if (sel == 0) return g_st0;
    if (sel == 1) return g_st1;
    if (sel == 2) return g_acc;
    return g_rho;
}

// ---------------- software grid barrier (all blocks co-resident) ----------------
__device__ __forceinline__ void grid_barrier(unsigned int &sense)
{
    __threadfence();
    __syncthreads();
    if (threadIdx.x == 0) {
        sense ^= 1u;
        unsigned int a = atomicAdd(&g_bar_count, 1u);
        if (a == gridDim.x - 1) {
            g_bar_count = 0;
            __threadfence();
            g_bar_sense = sense;
        } else {
            while (g_bar_sense != sense) { }
        }
    }
    __syncthreads();
}

// ---------------- inline prep (block 0 only, parallel) ----------------
__device__ void prep_inline(int tid, char* smem,
                            const float* __restrict__ features,
                            const float* __restrict__ W1, const float* __restrict__ b1,
                            const float* __restrict__ W2, const float* __restrict__ b2,
                            const float* __restrict__ Hself, const float* __restrict__ Hcoup,
                            const float* __restrict__ rates)
{
    float* sOps = (float*)(smem + PR_OPS);
    float* sK   = (float*)(smem + PR_K);
    float* sB1  = (float*)(smem + PR_B1);
    float* sB2  = (float*)(smem + PR_B2);

    // MLP: 7 warps, lane handles hidden units l and l+32
    if (tid < 224) {
        int w = tid >> 5, l = tid & 31;
        float f0 = features[w*2+0], f1 = features[w*2+1];
        float o0 = 0.f, o1 = 0.f, o2 = 0.f, o3 = 0.f;
        #pragma unroll
        for (int t = 0; t < 2; t++) {
            int h = l + t*32;
            float v = fmaf(f0, W1[h], fmaf(f1, W1[64+h], b1[h]));
            v = fmaxf(v, 0.f);
            o0 = fmaf(v, W2[h*4+0], o0);
            o1 = fmaf(v, W2[h*4+1], o1);
            o2 = fmaf(v, W2[h*4+2], o2);
            o3 = fmaf(v, W2[h*4+3], o3);
        }
        #pragma unroll
        for (int off = 16; off; off >>= 1) {
            o0 += __shfl_xor_sync(0xFFFFFFFFu, o0, off);
            o1 += __shfl_xor_sync(0xFFFFFFFFu, o1, off);
            o2 += __shfl_xor_sync(0xFFFFFFFFu, o2, off);
            o3 += __shfl_xor_sync(0xFFFFFFFFu, o3, off);
        }
        if (l == 0) {
            sOps[w*4+0] = o0 + b2[0];
            sOps[w*4+1] = o1 + b2[1];
            sOps[w*4+2] = o2 + b2[2];
            sOps[w*4+3] = o3 + b2[3];
        }
    }
    __syncthreads();

    // singles (tid < 7)
    if (tid < NQ) {
        int i = tid;
        const float* Hs = Hself + i*4;
        float o0=sOps[i*4+0], o1=sOps[i*4+1], o2=sOps[i*4+2], o3=sOps[i*4+3];
        float G0 = o0*Hs[0] + o1*Hs[2];
        float G1 = o0*Hs[1] + o1*Hs[3];
        float G2 = o2*Hs[0] + o3*Hs[2];
        float G3 = o2*Hs[1] + o3*Hs[3];
        g_Hs1[i][0] = 2.f*G0; g_Hs1[i][1] = G1+G2; g_Hs1[i][2] = G2+G1; g_Hs1[i][3] = 2.f*G3;
        const float* rr = rates + (i*NQ+i)*16;
        float B[4];
        B[0] = sqrtf(fabsf(rr[0]))*o0;
        B[1] = sqrtf(fabsf(rr[1]))*o1;
        B[2] = sqrtf(fabsf(rr[4]))*o2;
        B[3] = sqrtf(fabsf(rr[5]))*o3;
        g_Cs1[i][0] = B[0]*B[0]+B[2]*B[2];
        g_Cs1[i][1] = B[0]*B[1]+B[2]*B[3];
        g_Cs1[i][2] = B[1]*B[0]+B[3]*B[2];
        g_Cs1[i][3] = B[1]*B[1]+B[3]*B[3];
        for (int a=0;a<2;a++)
          for (int b=0;b<2;b++)
            for (int ap=0;ap<2;ap++)
              for (int bp=0;bp<2;bp++)
                g_Ss1[i][((a*2+b)*2+ap)*2+bp] = B[a*2+ap]*B[b*2+bp];
    }

    // pair K/B1/B2 entries (tid < 336)
    if (tid < NPAIR*16) {
        int p = tid >> 4, uv = tid & 15;
        int i = c_pi[p], j = c_pj[p];
        int u = uv >> 2, v = uv & 3;
        float kv = sOps[i*4+(u>>1)*2+(v>>1)] * sOps[j*4+(u&1)*2+(v&1)];
        sK[p*16+uv]  = kv;
        sB1[p*16+uv] = sqrtf(fabsf(rates[(i*NQ+j)*16 + uv])) * kv;
        int us = ((u&1)<<1)|(u>>1), vs = ((v&1)<<1)|(v>>1);
        float kv2 = sOps[j*4+(us>>1)*2+(vs>>1)] * sOps[i*4+(us&1)*2+(vs&1)];
        sB2[p*16+uv] = sqrtf(fabsf(rates[(j*NQ+i)*16 + us*4+vs])) * kv2;
    }
    __syncthreads();

    // Hp, Cp (tid < 336)
    if (tid < NPAIR*16) {
        int p = tid >> 4, uv = tid & 15;
        int u = uv >> 2, v = uv & 3;
        int i = c_pi[p], j = c_pj[p];
        const float* Hc = Hcoup + (i*NQ+j)*16;
        float s = 0.f, c = 0.f;
        #pragma unroll
        for (int k = 0; k < 4; k++) {
            s += sK[p*16+u*4+k]*Hc[k*4+v] + sK[p*16+v*4+k]*Hc[k*4+u];
            c += sB1[p*16+k*4+u]*sB1[p*16+k*4+v] + sB2[p*16+k*4+u]*sB2[p*16+k*4+v];
        }
        g_Hp[p][uv] = s;
        g_Cp[p][uv] = c;
    }

    // Sp table (all threads)
    for (int e = tid; e < NPAIR*256; e += NTHR) {
        int p = e >> 8, r = e & 255;
        int u = (r>>6)&3, v = (r>>4)&3, ap = (r>>2)&3, bp = r&3;
        g_Sp[p][r] = sB1[p*16+u*4+ap]*sB1[p*16+v*4+bp] + sB2[p*16+u*4+ap]*sB2[p*16+v*4+bp];
    }
}

// ---------------- templated per-q stage compute ----------------
template<int Q>
__device__ __forceinline__ void comp_stage(const float2* __restrict__ sRho,
                                           const float2* __restrict__ sAcol,
                                           const float2* __restrict__ sArow,
                                           const float*  __restrict__ sSx,
                                           const float*  __restrict__ sSsx,
                                           int x, int y, float& re, float& im)
{
    // sparse dense part
    #pragma unroll
    for (int k = ct_k0(Q); k < ct_k1(Q); k++) {
        const int d = ct_dd(k);
        float2 c1 = sArow[k];
        float2 r1 = sRho[(k<<7)+y];
        re = fmaf(c1.x, r1.x, re); re = fmaf(-c1.y, r1.y, re);
        im = fmaf(c1.x, r1.y, im); im = fmaf( c1.y, r1.x, im);
        float2 c2 = sAcol[(k<<7)+y];
        float2 r2 = sRho[y ^ d];
        re = fmaf(c2.x, r2.x, re); re = fmaf(-c2.y, r2.y, re);
        im = fmaf(c2.x, r2.y, im); im = fmaf( c2.y, r2.x, im);
    }
    // pair superoperators
    #pragma unroll
    for (int p = ct_p0(Q); p < ct_p1(Q); p++) {
        const int mi = ct_mi(p), mj = ct_mj(p), m = mi|mj;
        int yl = (((y&mi)!=0)<<1)|((y&mj)!=0);
        int xm = x & m;
        int xr0 = ((int)c_lut[xm])    << 7;
        int xr1 = ((int)c_lut[xm^mj]) << 7;
        int xr2 = ((int)c_lut[xm^mi]) << 7;
        int xr3 = ((int)c_lut[xm^m])  << 7;
        int y0 = y & ~m;
        int yc0 = y0, yc1 = y0 + mj, yc2 = y0 + mi, yc3 = y0 + m;
        const float4* Sp = reinterpret_cast<const float4*>(sSx + p*64 + yl*16);
        float4 s0 = Sp[0], s1 = Sp[1], s2 = Sp[2], s3 = Sp[3];
        float2 r;
        r = sRho[xr0+yc0]; re = fmaf(s0.x,r.x,re); im = fmaf(s0.x,r.y,im);
        r = sRho[xr0+yc1]; re = fmaf(s0.y,r.x,re); im = fmaf(s0.y,r.y,im);
        r = sRho[xr0+yc2]; re = fmaf(s0.z,r.x,re); im = fmaf(s0.z,r.y,im);
        r = sRho[xr0+yc3]; re = fmaf(s0.w,r.x,re); im = fmaf(s0.w,r.y,im);
        r = sRho[xr1+yc0]; re = fmaf(s1.x,r.x,re); im = fmaf(s1.x,r.y,im);
        r = sRho[xr1+yc1]; re = fmaf(s1.y,r.x,re); im = fmaf(s1.y,r.y,im);
        r = sRho[xr1+yc2]; re = fmaf(s1.z,r.x,re); im = fmaf(s1.z,r.y,im);
        r = sRho[xr1+yc3]; re = fmaf(s1.w,r.x,re); im = fmaf(s1.w,r.y,im);
        r = sRho[xr2+yc0]; re = fmaf(s2.x,r.x,re); im = fmaf(s2.x,r.y,im);
        r = sRho[xr2+yc1]; re = fmaf(s2.y,r.x,re); im = fmaf(s2.y,r.y,im);
        r = sRho[xr2+yc2]; re = fmaf(s2.z,r.x,re); im = fmaf(s2.z,r.y,im);
        r = sRho[xr2+yc3]; re = fmaf(s2.w,r.x,re); im = fmaf(s2.w,r.y,im);
        r = sRho[xr3+yc0]; re = fmaf(s3.x,r.x,re); im = fmaf(s3.x,r.y,im);
        r = sRho[xr3+yc1]; re = fmaf(s3.y,r.x,re); im = fmaf(s3.y,r.y,im);
        r = sRho[xr3+yc2]; re = fmaf(s3.z,r.x,re); im = fmaf(s3.z,r.y,im);
        r = sRho[xr3+yc3]; re = fmaf(s3.w,r.x,re); im = fmaf(s3.w,r.y,im);
    }
    // single-site superoperators
    #pragma unroll
    for (int i = ct_s0(Q); i < ct_s1(Q); i++) {
        const int mi = ct_sb(i);
        int yl = (y&mi)!=0;
        int xmi = x & mi;
        int xb0 = ((int)c_lut[xmi])    << 7;
        int xb1 = ((int)c_lut[xmi^mi]) << 7;
        int y0 = y & ~mi;
        const float* Ss = sSsx + i*8 + yl*4;
        float s0 = Ss[0], s1 = Ss[1], s2 = Ss[2], s3 = Ss[3];
        float2 r;
        r = sRho[xb0 + y0];      re = fmaf(s0,r.x,re); im = fmaf(s0,r.y,im);
        r = sRho[xb0 + y0 + mi]; re = fmaf(s1,r.x,re); im = fmaf(s1,r.y,im);
        r = sRho[xb1 + y0];      re = fmaf(s2,r.x,re); im = fmaf(s2,r.y,im);
        r = sRho[xb1 + y0 + mi]; re = fmaf(s3,r.x,re); im = fmaf(s3,r.y,im);
    }
}

// ---------------- the single fused kernel ----------------
__global__ void __launch_bounds__(NTHR, 1)
solve_kernel(float* __restrict__ out, const float* __restrict__ t_eval,
             const float* __restrict__ features,
             const float* __restrict__ W1, const float* __restrict__ b1,
             const float* __restrict__ W2, const float* __restrict__ b2,
             const float* __restrict__ Hself, const float* __restrict__ Hcoup,
             const float* __restrict__ rates, const float* __restrict__ rho0)
{
    extern __shared__ __align__(16) char smem[];
    float2* sRho   = (float2*)(smem + SM_RHO);
    float2* sAcol  = (float2*)(smem + SM_ACOL);
    float2* sArow  = (float2*)(smem + SM_AROW);
    float2* sPart  = (float2*)(smem + SM_PART);
    float*  sSx    = (float*)(smem + SM_SX);
    float*  sSsx   = (float*)(smem + SM_SSX);

    int x   = blockIdx.x;
    int tid = threadIdx.x;
    int y   = tid & 127;
    int q   = tid >> 7;
    unsigned int sense = 0;

    // ---- phase A: prep (block 0 only) ----
    if (x == 0)
        prep_inline(tid, smem, features, W1, b1, W2, b2, Hself, Hcoup, rates);
    grid_barrier(sense);

    // ---- phase B: build A sparse tables + init rho/out0 (each block = its row) ----
    if (tid < D) {
        int yb = tid;
        int d = x ^ yb;
        float Hv = 0.f, Mv = 0.f;
        #pragma unroll
        for (int i = 0; i < NQ; i++) {
            int mi = 1<<(6-i);
            if ((d & (127 ^ mi)) == 0) {
                int xl = (x>>(6-i))&1, yl = (yb>>(6-i))&1;
                Hv += g_Hs1[i][xl*2+yl];
                Mv += g_Cs1[i][xl*2+yl];
            }
        }
        #pragma unroll
        for (int p = 0; p < NPAIR; p++) {
            int mi = c_mi[p], mj = c_mj[p];
            if ((d & (127 ^ (mi|mj))) == 0) {
                int xl = (((x&mi)!=0)<<1)|((x&mj)!=0);
                int yl = (((yb&mi)!=0)<<1)|((yb&mj)!=0);
                Hv += g_Hp[p][xl*4+yl];
                Mv += g_Cp[p][xl*4+yl];
            }
        }
        int k = c_lut[d];
        if (k < NOFF) {
            g_Arow[(k<<7)+x] = make_float2(-0.5f*Mv, -Hv);
            g_Acol[(k<<7)+x] = make_float2(-0.5f*Mv,  Hv);
        }
        float v = rho0[(x<<7)+yb];
        g_rho[(x<<7)+yb] = make_float2(v, 0.f);
        out[(x<<7)+yb] = v;
    }
    grid_barrier(sense);

    // ---- phase C: stage invariant tables ----
    {
        const float4* gv = (const float4*)g_Acol;
        float4* sv = (float4*)sAcol;
        for (int t = tid; t < NOFF*64; t += NTHR) sv[t] = __ldcg(&gv[t]);
    }
    if (tid < NOFF) sArow[tid] = __ldcg(&g_Arow[(tid<<7) + x]);
    for (int t = tid; t < NPAIR*64; t += NTHR) {
        int p = t >> 6;
        int mi = c_mi[p], mj = c_mj[p];
        int xl = (((x&mi)!=0)<<1)|((x&mj)!=0);
        sSx[t] = __ldcg(&g_Sp[p][xl*64 + (t & 63)]);
    }
    if (tid >= NTHR-NQ*8) {
        int t = tid - (NTHR-NQ*8);
        int i = t >> 3;
        int mi = 1<<(6-i);
        int xl = (x & mi) != 0;
        sSsx[t] = __ldcg(&g_Ss1[i][xl*8 + (t & 7)]);
    }

    // ---- phase D: 16 RK4 stages ----
    for (int s = 0; s < NSTAGE; s++) {
        int j = s & 3, step = s >> 2;
        const float2* in = rsv(cs_in[j]);

        {
            const float4* inv = (const float4*)in;
            float4* srv = (float4*)sRho;
            for (int t = tid; t < NOFF*64; t += NTHR) {
                int k = t >> 6, c4 = t & 63;
                srv[t] = __ldcg(&inv[((x ^ c_dd[k])<<6) + c4]);
            }
        }
        __syncthreads();

        float re = 0.f, im = 0.f;
        switch (q) {
            case 0:  comp_stage<0>(sRho, sAcol, sArow, sSx, sSsx, x, y, re, im); break;
            case 1:  comp_stage<1>(sRho, sAcol, sArow, sSx, sSsx, x, y, re, im); break;
            case 2:  comp_stage<2>(sRho, sAcol, sArow, sSx, sSsx, x, y, re, im); break;
            case 3:  comp_stage<3>(sRho, sAcol, sArow, sSx, sSsx, x, y, re, im); break;
            default: comp_stage<4>(sRho, sAcol, sArow, sSx, sSsx, x, y, re, im); break;
        }

        if (q != 0) sPart[((q-1)<<7) + y] = make_float2(re, im);
        __syncthreads();
        if (q == 0) {
            float2 p1 = sPart[y], p2 = sPart[128+y], p3 = sPart[256+y], p4 = sPart[384+y];
            re += p1.x + p2.x + p3.x + p4.x;
            im += p1.y + p2.y + p3.y + p4.y;
            int idx = (x<<7) + y;
            float dt = __ldg(&t_eval[step+1]) - __ldg(&t_eval[step]);
            const float2* sb = rsv(cs_sb[j]);
            float2* so = rsvw(cs_so[j]);
            float cs = cs_fs[j]*dt;
            float2 sv = __ldcg(&sb[idx]);
            float2 ov = make_float2(fmaf(cs, re, sv.x), fmaf(cs, im, sv.y));
            so[idx] = ov;
            if (j == 3) out[(step+1)*D*D + idx] = ov.x;
            float fa = cs_fa[j];
            if (fa != 0.f) {
                const float2* ab = rsv(cs_ab[j]);
                float2 av = __ldcg(&ab[idx]);
                float ca = fa*dt;
                g_acc[idx] = make_float2(fmaf(ca, re, av.x), fmaf(ca, im, av.y));
            }
        }
        grid_barrier(sense);   // 18 barriers total (even): sense ends 0, replay-safe
    }
}

// ---------------- launcher ----------------
extern "C" void kernel_launch(void* const* d_in, const int* in_sizes, int n_in,
                              void* d_out, int out_size)
{
    const float *features=0, *t_eval=0, *W1=0, *b1=0, *W2=0, *b2=0;
    const float *Hself=0, *Hcoup=0, *rates=0, *rho0=0;
    int n784 = 0;
    for (int i = 0; i < n_in; i++) {
        const float* p = (const float*)d_in[i];
        switch (in_sizes[i]) {
            case 14:    features = p; break;
            case 5:     t_eval   = p; break;
            case 128:   W1       = p; break;
            case 64:    b1       = p; break;
            case 256:   W2       = p; break;
            case 4:     b2       = p; break;
            case 28:    Hself    = p; break;
            case 784:   if (n784++ == 0) Hcoup = p; else rates = p; break;
            case 16384: rho0     = p; break;
            default: break;
        }
    }
    if (!features) features = (const float*)d_in[0];
    if (!t_eval)   t_eval   = (const float*)d_in[1];
    if (!W1)       W1       = (const float*)d_in[2];
    if (!b1)       b1       = (const float*)d_in[3];
    if (!W2)       W2       = (const float*)d_in[4];
    if (!b2)       b2       = (const float*)d_in[5];
    if (!Hself)    Hself    = (const float*)d_in[6];
    if (!Hcoup)    Hcoup    = (const float*)d_in[7];
    if (!rates)    rates    = (const float*)d_in[8];
    if (!rho0)     rho0     = (const float*)d_in[9];

    float* out = (float*)d_out;   // float32 real output, (5,128,128)

    static int attrDone = 0;
    if (!attrDone) {
        cudaFuncSetAttribute(solve_kernel, cudaFuncAttributeMaxDynamicSharedMemorySize, SMEM_BYTES);
        attrDone = 1;
    }

    solve_kernel<<<D, NTHR, SMEM_BYTES>>>(out, t_eval, features, W1, b1, W2, b2,
                                          Hself, Hcoup, rates, rho0);
    (void)out_size;
}